// round 13
// baseline (speedup 1.0000x reference)
#include <cuda_runtime.h>
#include <cuda_bf16.h>
#include <cstdint>

typedef unsigned long long u64;

#define B_    8
#define CM_   64
#define CQ_   64
#define CIN_  128
#define CO_   64
#define H_    128
#define W_    128
#define K_    9
#define JOFF_ 27
#define HW_   (H_*W_)

// Scratch (no cudaMalloc allowed).
__device__ __align__(16) float  g_off[B_*JOFF_*HW_];      // [b][j][h][w]
__device__ __align__(16) __nv_bfloat16 g_wbf[K_*2*4096];  // deform W: [tap][hi|lo][n][k]
__device__ __align__(16) __nv_bfloat16 g_wobf[K_*2*2*2048]; // offset W: [tap][half][hi|lo][n=32][k=64]
__device__ __align__(16) float  g_xT[B_*HW_*CIN_];        // channel-last concat [b][h][w][c=128]

__device__ __forceinline__ uint32_t smem_u32(const void* p) {
    uint32_t a;
    asm("{ .reg .u64 t; cvta.to.shared.u64 t, %1; cvt.u32.u64 %0, t; }" : "=r"(a) : "l"(p));
    return a;
}

#define SWB(row, colb) ((row)*128 + ((((colb) >> 4) ^ ((row) & 7)) << 4) + ((colb) & 15))

__device__ __forceinline__ void ldsm_x4(uint32_t a[4], uint32_t addr) {
    asm volatile("ldmatrix.sync.aligned.m8n8.x4.shared.b16 {%0,%1,%2,%3}, [%4];"
        : "=r"(a[0]), "=r"(a[1]), "=r"(a[2]), "=r"(a[3]) : "r"(addr));
}
__device__ __forceinline__ void ldsm_x2(uint32_t b[2], uint32_t addr) {
    asm volatile("ldmatrix.sync.aligned.m8n8.x2.shared.b16 {%0,%1}, [%2];"
        : "=r"(b[0]), "=r"(b[1]) : "r"(addr));
}
__device__ __forceinline__ void mma16816(float c[4], const uint32_t a[4], const uint32_t b[2]) {
    asm volatile("mma.sync.aligned.m16n8k16.row.col.f32.bf16.bf16.f32 "
        "{%0,%1,%2,%3}, {%4,%5,%6,%7}, {%8,%9}, {%0,%1,%2,%3};"
        : "+f"(c[0]), "+f"(c[1]), "+f"(c[2]), "+f"(c[3])
        : "r"(a[0]), "r"(a[1]), "r"(a[2]), "r"(a[3]), "r"(b[0]), "r"(b[1]));
}

// split fp32 -> bf16 hi + residual lo
__device__ __forceinline__ void bf16split(float s, uint16_t &hi, uint16_t &lo) {
    __nv_bfloat16 h = __float2bfloat16_rn(s);
    __nv_bfloat16 l = __float2bfloat16_rn(s - __bfloat162float(h));
    hi = __bfloat16_as_ushort(h);
    lo = __bfloat16_as_ushort(l);
}

// ---------------------------------------------------------------------------
// Prep: deform weights (bf16 hi/lo [n][k]) + offset weights
// ([tap][half][hi|lo][n=32 pad][k=64]).
// ---------------------------------------------------------------------------
#define N_WB   (K_*64*64)       // 36864
#define N_WO   (K_*2*32*64)     // 36864
__global__ void prep_weights_kernel(const float* __restrict__ w_off,
                                    const float* __restrict__ w_def) {
    int i = blockIdx.x * 256 + threadIdx.x;
    if (i < N_WB) {
        int tap = i / 4096;
        int r = i - tap*4096;
        int n = r >> 6;
        int c = r & 63;
        float w = w_def[(n*CM_ + c)*K_ + tap];
        __nv_bfloat16 hi = __float2bfloat16_rn(w);
        __nv_bfloat16 lo = __float2bfloat16_rn(w - __bfloat162float(hi));
        g_wbf[tap*8192 + n*64 + c]        = hi;
        g_wbf[tap*8192 + 4096 + n*64 + c] = lo;
    } else if (i < N_WB + N_WO) {
        int i2 = i - N_WB;
        int tap = i2 / 4096;
        int r = i2 - tap*4096;
        int half = r >> 11;
        int r2 = r & 2047;
        int n = r2 >> 6;
        int k = r2 & 63;
        int c = half*64 + k;
        float w = (n < JOFF_) ? w_off[(n*CIN_ + c)*K_ + tap] : 0.f;
        __nv_bfloat16 hi = __float2bfloat16_rn(w);
        __nv_bfloat16 lo = __float2bfloat16_rn(w - __bfloat162float(hi));
        g_wobf[tap*8192 + half*4096 + n*64 + k]        = hi;
        g_wobf[tap*8192 + half*4096 + 2048 + n*64 + k] = lo;
    }
}

// ---------------------------------------------------------------------------
// Transpose concat(mem,que) -> channel-last g_xT[b][h][w][c=128].
// ---------------------------------------------------------------------------
__global__ __launch_bounds__(256) void transpose_x_kernel(
        const float* __restrict__ mem, const float* __restrict__ que) {
    __shared__ float tile[64][129];
    const int bh = blockIdx.x;
    const int b = bh >> 7, h = bh & 127;
    const int tid = threadIdx.x;
    #pragma unroll
    for (int pass = 0; pass < 2; pass++) {
        const float* src = (pass ? que + (size_t)b*CQ_*HW_ : mem + (size_t)b*CM_*HW_) + h*W_;
        #pragma unroll
        for (int m = 0; m < 32; m++) {
            int e = tid + 256*m;
            int c = e >> 7, w = e & 127;
            tile[c][w] = src[(size_t)c*HW_ + w];
        }
        __syncthreads();
        float* dst = g_xT + ((size_t)b*HW_ + h*W_)*CIN_ + pass*64;
        #pragma unroll
        for (int m = 0; m < 32; m++) {
            int e = tid + 256*m;
            int w = e >> 6, c = e & 63;
            dst[(size_t)w*CIN_ + c] = tile[c][w];
        }
        __syncthreads();
    }
}

// ---------------------------------------------------------------------------
// Offset conv: producer/consumer, double-buffered. Warps 0-3 consumers
// (M=32 each: pixels 32w..32w+31, all 32 outs); warps 4-7 producers stage
// A (shifted rows of g_xT, bf16 hi/lo) + B for stage s+1. One sync/stage.
// Dynamic smem 80KB: A[2]{hi16K,lo16K} | B[2]{hi4K,lo4K}.
// ---------------------------------------------------------------------------
__global__ __launch_bounds__(256, 2) void offset_mma_kernel(const float* __restrict__ b_off) {
    extern __shared__ __align__(16) char smem[];
    // A buf: buf*32768 (hi +0, lo +16384); B buf: 65536 + buf*8192 (hi +0, lo +4096)

    const int tid  = threadIdx.x;
    const int lane = tid & 31;
    const int wrp  = tid >> 5;
    const int bh   = blockIdx.x;
    const int b    = bh >> 7;
    const int h    = bh & 127;
    const bool consumer = (wrp < 4);

    const char* xTb = (const char*)(g_xT + (size_t)b*HW_*CIN_);

    float C[2][4][4];
    uint32_t abase_u[2], bbase_u[2];
    #pragma unroll
    for (int p = 0; p < 2; p++) {
        abase_u[p] = smem_u32(smem + p*32768);
        bbase_u[p] = smem_u32(smem + 65536 + p*8192);
    }

    // producer constants
    const int ptid  = tid - 128;       // 0..127 for producers
    const int pw    = wrp - 4;         // 0..3
    const int plane = lane >> 4;
    const int chunk = lane & 15;

    #define OPRODUCE(st, buf) do {                                            \
        const int tap = (st) >> 1;                                            \
        const int hh  = (st) & 1;                                             \
        const int ky  = tap / 3, kx = tap - ky*3;                             \
        const int rowv = h + ky - 1;                                          \
        const bool rowok = (rowv >= 0 && rowv < H_);                          \
        char* Ahi = smem + (buf)*32768;                                       \
        char* Alo = Ahi + 16384;                                              \
        char* Bhi = smem + 65536 + (buf)*8192;                                \
        char* Blo = Bhi + 4096;                                               \
        const uint4* bsrc = (const uint4*)(g_wobf + (size_t)tap*8192 + hh*4096); \
        _Pragma("unroll")                                                     \
        for (int m = 0; m < 4; m++) {                                         \
            int e = ptid + 128*m;                                             \
            uint4 v = bsrc[e];                                                \
            int e2 = e & 255;                                                 \
            int n = e2 >> 3, kc = e2 & 7;                                     \
            char* dst = (e < 256) ? Bhi : Blo;                                \
            *(uint4*)(dst + n*128 + ((kc ^ (n & 7)) << 4)) = v;               \
        }                                                                     \
        const char* xrow = xTb + ((size_t)rowv*W_)*512 + hh*256;              \
        _Pragma("unroll")                                                     \
        for (int i = 0; i < 16; i++) {                                        \
            const int sub = 2*i + plane;                                      \
            const int px  = 32*pw + sub;                                      \
            const int ww  = px + kx - 1;                                      \
            float4 v = make_float4(0.f, 0.f, 0.f, 0.f);                       \
            if (rowok && ww >= 0 && ww < W_)                                  \
                v = *(const float4*)(xrow + (size_t)ww*512 + chunk*16);       \
            uint16_t h0,h1,h2,h3,l0,l1,l2,l3;                                 \
            bf16split(v.x, h0, l0);                                           \
            bf16split(v.y, h1, l1);                                           \
            bf16split(v.z, h2, l2);                                           \
            bf16split(v.w, h3, l3);                                           \
            u64 hiq = ((u64)h3 << 48) | ((u64)h2 << 32) | ((u64)h1 << 16) | h0; \
            u64 loq = ((u64)l3 << 48) | ((u64)l2 << 32) | ((u64)l1 << 16) | l0; \
            const uint32_t off = SWB(px, chunk*8);                            \
            *(u64*)(Ahi + off) = hiq;                                         \
            *(u64*)(Alo + off) = loq;                                         \
        }                                                                     \
    } while (0)

    if (consumer) {
        #pragma unroll
        for (int mt = 0; mt < 2; mt++)
            #pragma unroll
            for (int nt = 0; nt < 4; nt++)
                #pragma unroll
                for (int i = 0; i < 4; i++) C[mt][nt][i] = 0.f;
    } else {
        OPRODUCE(0, 0);
    }
    __syncthreads();

    for (int st = 0; st < 18; st++) {
        const int p = st & 1;
        if (consumer) {
            const uint32_t ahi_u = abase_u[p], alo_u = abase_u[p] + 16384;
            const uint32_t bhi_u = bbase_u[p], blo_u = bbase_u[p] + 4096;
            const int arow0 = 32*wrp + (lane & 15);
            const int arow1 = arow0 + 16;
            const int acolh = ((lane >> 4) & 1) * 16;
            const int brow_base = lane & 7;
            const int bcolh = ((lane >> 3) & 1) * 16;
            #pragma unroll
            for (int ks = 0; ks < 4; ks++) {
                uint32_t Ah0[4], Al0[4], Ah1[4], Al1[4];
                uint32_t a0 = SWB(arow0, ks*32 + acolh);
                uint32_t a1 = SWB(arow1, ks*32 + acolh);
                ldsm_x4(Ah0, ahi_u + a0);
                ldsm_x4(Al0, alo_u + a0);
                ldsm_x4(Ah1, ahi_u + a1);
                ldsm_x4(Al1, alo_u + a1);
                #pragma unroll
                for (int nt = 0; nt < 4; nt++) {
                    const int brow = nt*8 + brow_base;
                    uint32_t boff = SWB(brow, ks*32 + bcolh);
                    uint32_t Bh[2], Bl[2];
                    ldsm_x2(Bh, bhi_u + boff);
                    ldsm_x2(Bl, blo_u + boff);
                    mma16816(C[0][nt], Ah0, Bh);
                    mma16816(C[0][nt], Al0, Bh);
                    mma16816(C[0][nt], Ah0, Bl);
                    mma16816(C[1][nt], Ah1, Bh);
                    mma16816(C[1][nt], Al1, Bh);
                    mma16816(C[1][nt], Ah1, Bl);
                }
            }
        } else {
            if (st + 1 < 18) OPRODUCE(st + 1, p ^ 1);
        }
        __syncthreads();
    }
    #undef OPRODUCE

    if (consumer) {
        const int g = lane >> 2, t4 = lane & 3;
        float* ob = g_off + (size_t)b*JOFF_*HW_ + h*W_;
        #pragma unroll
        for (int mt = 0; mt < 2; mt++) {
            const int m0 = 32*wrp + mt*16 + g;
            #pragma unroll
            for (int nt = 0; nt < 4; nt++) {
                const int n0 = nt*8 + 2*t4;
                if (n0 < JOFF_) {
                    float bi = b_off[n0];
                    ob[(size_t)n0*HW_ + m0]     = C[mt][nt][0] + bi;
                    ob[(size_t)n0*HW_ + m0 + 8] = C[mt][nt][2] + bi;
                }
                if (n0 + 1 < JOFF_) {
                    float bi = b_off[n0 + 1];
                    ob[(size_t)(n0+1)*HW_ + m0]     = C[mt][nt][1] + bi;
                    ob[(size_t)(n0+1)*HW_ + m0 + 8] = C[mt][nt][3] + bi;
                }
            }
        }
    }
}

// ---------------------------------------------------------------------------
// Deformable conv: producer/consumer, double-buffered. Warps 0-3 consumers
// (M=32 each, 64 outs); warps 4-7 producers (bilinear gather, channel-last,
// half-warp per pixel coalescing). One sync/tap.
// Dynamic smem 96KB: A[2]{hi16K,lo16K} | B[2]{hi8K,lo8K}.
// ---------------------------------------------------------------------------
__global__ __launch_bounds__(256, 2) void deform_mma_kernel(float* __restrict__ out) {
    extern __shared__ __align__(16) char smem[];
    // A buf: buf*32768 (hi +0, lo +16384); B buf: 65536 + buf*16384 (hi +0, lo +8192)

    const int tid  = threadIdx.x;
    const int lane = tid & 31;
    const int wrp  = tid >> 5;
    const int bh   = blockIdx.x;
    const int b    = bh >> 7;
    const int h    = bh & 127;
    const bool consumer = (wrp < 4);

    const char* memTb = (const char*)(g_xT + (size_t)b*HW_*CIN_);  // ch 0-63 = mem
    const float* offrow = g_off + (size_t)b*JOFF_*HW_ + h*W_;

    uint32_t abase_u[2], bbase_u[2];
    #pragma unroll
    for (int p = 0; p < 2; p++) {
        abase_u[p] = smem_u32(smem + p*32768);
        bbase_u[p] = smem_u32(smem + 65536 + p*16384);
    }

    float C[2][8][4];

    const int ptid  = tid - 128;
    const int pw    = wrp - 4;
    const int plane = lane >> 4;
    const int chunk = lane & 15;

    #define DPRODUCE(t, buf) do {                                             \
        char* Ahi = smem + (buf)*32768;                                       \
        char* Alo = Ahi + 16384;                                              \
        char* Bhi = smem + 65536 + (buf)*16384;                               \
        char* Blo = Bhi + 8192;                                               \
        /* params: lane l -> pixel 32*pw + l */                               \
        float W00, W01, W10, W11;                                             \
        int   B00, B01, B10, B11;                                             \
        {                                                                     \
            const int ppx = 32*pw + lane;                                     \
            const float* op = offrow + ppx;                                   \
            float dy  = op[(2*(t))*HW_];                                      \
            float dx  = op[(2*(t)+1)*HW_];                                    \
            float msk = op[(18+(t))*HW_];                                     \
            float py  = (float)(h + ((t)/3) - 1) + dy;                        \
            float pxx = (float)(ppx + ((t) - ((t)/3)*3) - 1) + dx;            \
            float y0f = floorf(py), x0f = floorf(pxx);                        \
            float fy = py - y0f, fx = pxx - x0f;                              \
            int y0 = (int)y0f, x0 = (int)x0f;                                 \
            int y1 = y0 + 1,   x1 = x0 + 1;                                   \
            float vy0 = (y0 >= 0 && y0 < H_) ? 1.f : 0.f;                     \
            float vy1 = (y1 >= 0 && y1 < H_) ? 1.f : 0.f;                     \
            float vx0 = (x0 >= 0 && x0 < W_) ? 1.f : 0.f;                     \
            float vx1 = (x1 >= 0 && x1 < W_) ? 1.f : 0.f;                     \
            int y0c = min(max(y0, 0), H_-1), y1c = min(max(y1, 0), H_-1);     \
            int x0c = min(max(x0, 0), W_-1), x1c = min(max(x1, 0), W_-1);     \
            W00 = (1.f-fy)*(1.f-fx)*msk*vy0*vx0;                              \
            W01 = (1.f-fy)*fx      *msk*vy0*vx1;                              \
            W10 = fy      *(1.f-fx)*msk*vy1*vx0;                              \
            W11 = fy      *fx      *msk*vy1*vx1;                              \
            B00 = (y0c*W_ + x0c) << 9;                                        \
            B01 = (y0c*W_ + x1c) << 9;                                        \
            B10 = (y1c*W_ + x0c) << 9;                                        \
            B11 = (y1c*W_ + x1c) << 9;                                        \
        }                                                                     \
        const uint4* bsrc = (const uint4*)(g_wbf + (size_t)(t)*8192);         \
        _Pragma("unroll")                                                     \
        for (int m = 0; m < 8; m++) {                                         \
            int e = ptid + 128*m;                                             \
            uint4 v = bsrc[e];                                                \
            int e2 = e & 511;                                                 \
            int n = e2 >> 3, kc = e2 & 7;                                     \
            char* dst = (e < 512) ? Bhi : Blo;                                \
            *(uint4*)(dst + n*128 + ((kc ^ (n & 7)) << 4)) = v;               \
        }                                                                     \
        _Pragma("unroll")                                                     \
        for (int i = 0; i < 16; i++) {                                        \
            const int sub = 2*i + plane;                                      \
            float w00 = __shfl_sync(0xffffffffu, W00, sub);                   \
            float w01 = __shfl_sync(0xffffffffu, W01, sub);                   \
            float w10 = __shfl_sync(0xffffffffu, W10, sub);                   \
            float w11 = __shfl_sync(0xffffffffu, W11, sub);                   \
            int   b00 = __shfl_sync(0xffffffffu, B00, sub);                   \
            int   b01 = __shfl_sync(0xffffffffu, B01, sub);                   \
            int   b10 = __shfl_sync(0xffffffffu, B10, sub);                   \
            int   b11 = __shfl_sync(0xffffffffu, B11, sub);                   \
            const int cb = chunk * 16;                                        \
            float4 c00 = *(const float4*)(memTb + b00 + cb);                  \
            float4 c01 = *(const float4*)(memTb + b01 + cb);                  \
            float4 c10 = *(const float4*)(memTb + b10 + cb);                  \
            float4 c11 = *(const float4*)(memTb + b11 + cb);                  \
            float s0 = w00*c00.x + w01*c01.x + w10*c10.x + w11*c11.x;         \
            float s1 = w00*c00.y + w01*c01.y + w10*c10.y + w11*c11.y;         \
            float s2 = w00*c00.z + w01*c01.z + w10*c10.z + w11*c11.z;         \
            float s3 = w00*c00.w + w01*c01.w + w10*c10.w + w11*c11.w;         \
            uint16_t h0,h1,h2,h3,l0,l1,l2,l3;                                 \
            bf16split(s0, h0, l0);                                            \
            bf16split(s1, h1, l1);                                            \
            bf16split(s2, h2, l2);                                            \
            bf16split(s3, h3, l3);                                            \
            u64 hiq = ((u64)h3 << 48) | ((u64)h2 << 32) | ((u64)h1 << 16) | h0; \
            u64 loq = ((u64)l3 << 48) | ((u64)l2 << 32) | ((u64)l1 << 16) | l0; \
            const int px = 32*pw + sub;                                       \
            const uint32_t off = SWB(px, chunk*8);                            \
            *(u64*)(Ahi + off) = hiq;                                         \
            *(u64*)(Alo + off) = loq;                                         \
        }                                                                     \
    } while (0)

    if (consumer) {
        #pragma unroll
        for (int mt = 0; mt < 2; mt++)
            #pragma unroll
            for (int nt = 0; nt < 8; nt++)
                #pragma unroll
                for (int i = 0; i < 4; i++) C[mt][nt][i] = 0.f;
    } else {
        DPRODUCE(0, 0);
    }
    __syncthreads();

    for (int t = 0; t < K_; t++) {
        const int p = t & 1;
        if (consumer) {
            const uint32_t ahi_u = abase_u[p], alo_u = abase_u[p] + 16384;
            const uint32_t bhi_u = bbase_u[p], blo_u = bbase_u[p] + 8192;
            const int arow0 = 32*wrp + (lane & 15);
            const int arow1 = arow0 + 16;
            const int acolh = ((lane >> 4) & 1) * 16;
            const int brow_base = lane & 7;
            const int bcolh = ((lane >> 3) & 1) * 16;
            #pragma unroll
            for (int ks = 0; ks < 4; ks++) {
                uint32_t Ah0[4], Al0[4], Ah1[4], Al1[4];
                uint32_t a0 = SWB(arow0, ks*32 + acolh);
                uint32_t a1 = SWB(arow1, ks*32 + acolh);
                ldsm_x4(Ah0, ahi_u + a0);
                ldsm_x4(Al0, alo_u + a0);
                ldsm_x4(Ah1, ahi_u + a1);
                ldsm_x4(Al1, alo_u + a1);
                #pragma unroll
                for (int nt = 0; nt < 8; nt++) {
                    const int brow = nt*8 + brow_base;
                    uint32_t boff = SWB(brow, ks*32 + bcolh);
                    uint32_t Bh[2], Bl[2];
                    ldsm_x2(Bh, bhi_u + boff);
                    ldsm_x2(Bl, blo_u + boff);
                    mma16816(C[0][nt], Ah0, Bh);
                    mma16816(C[0][nt], Al0, Bh);
                    mma16816(C[0][nt], Ah0, Bl);
                    mma16816(C[1][nt], Ah1, Bh);
                    mma16816(C[1][nt], Al1, Bh);
                    mma16816(C[1][nt], Ah1, Bl);
                }
            }
        } else {
            if (t + 1 < K_) DPRODUCE(t + 1, p ^ 1);
        }
        __syncthreads();
    }
    #undef DPRODUCE

    if (consumer) {
        const int g = lane >> 2, t4 = lane & 3;
        float* ob = out + (size_t)b*CO_*HW_ + h*W_;
        #pragma unroll
        for (int mt = 0; mt < 2; mt++) {
            const int m0 = 32*wrp + mt*16 + g;
            #pragma unroll
            for (int nt = 0; nt < 8; nt++) {
                const int n0 = nt*8 + 2*t4;
                ob[(size_t)n0*HW_ + m0]         = C[mt][nt][0];
                ob[(size_t)(n0+1)*HW_ + m0]     = C[mt][nt][1];
                ob[(size_t)n0*HW_ + m0 + 8]     = C[mt][nt][2];
                ob[(size_t)(n0+1)*HW_ + m0 + 8] = C[mt][nt][3];
            }
        }
    }
}

extern "C" void kernel_launch(void* const* d_in, const int* in_sizes, int n_in,
                              void* d_out, int out_size) {
    const float* mem   = (const float*)d_in[0];
    const float* que   = (const float*)d_in[1];
    const float* w_off = (const float*)d_in[2];
    const float* b_off = (const float*)d_in[3];
    const float* w_def = (const float*)d_in[4];
    float* out = (float*)d_out;

    cudaFuncSetAttribute(offset_mma_kernel,
                         cudaFuncAttributeMaxDynamicSharedMemorySize, 81920);
    cudaFuncSetAttribute(deform_mma_kernel,
                         cudaFuncAttributeMaxDynamicSharedMemorySize, 98304);

    prep_weights_kernel<<<(N_WB + N_WO + 255)/256, 256>>>(w_off, w_def);
    transpose_x_kernel<<<B_*H_, 256>>>(mem, que);
    offset_mma_kernel<<<B_*H_, 256, 81920>>>(b_off);
    deform_mma_kernel<<<B_*H_, 256, 98304>>>(out);
}

// round 14
// speedup vs baseline: 1.2116x; 1.2116x over previous
#include <cuda_runtime.h>
#include <cuda_bf16.h>
#include <cstdint>

typedef unsigned long long u64;

#define B_    8
#define CM_   64
#define CQ_   64
#define CIN_  128
#define CO_   64
#define H_    128
#define W_    128
#define K_    9
#define JOFF_ 27
#define HW_   (H_*W_)

// Scratch (no cudaMalloc allowed).
__device__ __align__(16) float  g_off[B_*JOFF_*HW_];      // [b][j][h][w]
__device__ __align__(16) __nv_bfloat16 g_wbf[K_*2*4096];  // deform W: [tap][hi|lo][n][k]
__device__ __align__(16) __nv_bfloat16 g_wobf[K_*2*2*2048]; // offset W: [tap][half][hi|lo][n=32][k=64]
__device__ __align__(16) float  g_xT[B_*HW_*CIN_];        // channel-last concat [b][h][w][c=128]

__device__ __forceinline__ uint32_t smem_u32(const void* p) {
    uint32_t a;
    asm("{ .reg .u64 t; cvta.to.shared.u64 t, %1; cvt.u32.u64 %0, t; }" : "=r"(a) : "l"(p));
    return a;
}

#define SWB(row, colb) ((row)*128 + ((((colb) >> 4) ^ ((row) & 7)) << 4) + ((colb) & 15))

__device__ __forceinline__ void ldsm_x4(uint32_t a[4], uint32_t addr) {
    asm volatile("ldmatrix.sync.aligned.m8n8.x4.shared.b16 {%0,%1,%2,%3}, [%4];"
        : "=r"(a[0]), "=r"(a[1]), "=r"(a[2]), "=r"(a[3]) : "r"(addr));
}
__device__ __forceinline__ void ldsm_x2(uint32_t b[2], uint32_t addr) {
    asm volatile("ldmatrix.sync.aligned.m8n8.x2.shared.b16 {%0,%1}, [%2];"
        : "=r"(b[0]), "=r"(b[1]) : "r"(addr));
}
__device__ __forceinline__ void mma16816(float c[4], const uint32_t a[4], const uint32_t b[2]) {
    asm volatile("mma.sync.aligned.m16n8k16.row.col.f32.bf16.bf16.f32 "
        "{%0,%1,%2,%3}, {%4,%5,%6,%7}, {%8,%9}, {%0,%1,%2,%3};"
        : "+f"(c[0]), "+f"(c[1]), "+f"(c[2]), "+f"(c[3])
        : "r"(a[0]), "r"(a[1]), "r"(a[2]), "r"(a[3]), "r"(b[0]), "r"(b[1]));
}

// split fp32 -> bf16 hi + residual lo
__device__ __forceinline__ void bf16split(float s, uint16_t &hi, uint16_t &lo) {
    __nv_bfloat16 h = __float2bfloat16_rn(s);
    __nv_bfloat16 l = __float2bfloat16_rn(s - __bfloat162float(h));
    hi = __bfloat16_as_ushort(h);
    lo = __bfloat16_as_ushort(l);
}

// ---------------------------------------------------------------------------
// Prep: deform weights (bf16 hi/lo [n][k]) + offset weights
// ([tap][half][hi|lo][n=32 pad][k=64]).
// ---------------------------------------------------------------------------
#define N_WB   (K_*64*64)       // 36864
#define N_WO   (K_*2*32*64)     // 36864
__global__ void prep_weights_kernel(const float* __restrict__ w_off,
                                    const float* __restrict__ w_def) {
    int i = blockIdx.x * 256 + threadIdx.x;
    if (i < N_WB) {
        int tap = i / 4096;
        int r = i - tap*4096;
        int n = r >> 6;
        int c = r & 63;
        float w = w_def[(n*CM_ + c)*K_ + tap];
        __nv_bfloat16 hi = __float2bfloat16_rn(w);
        __nv_bfloat16 lo = __float2bfloat16_rn(w - __bfloat162float(hi));
        g_wbf[tap*8192 + n*64 + c]        = hi;
        g_wbf[tap*8192 + 4096 + n*64 + c] = lo;
    } else if (i < N_WB + N_WO) {
        int i2 = i - N_WB;
        int tap = i2 / 4096;
        int r = i2 - tap*4096;
        int half = r >> 11;
        int r2 = r & 2047;
        int n = r2 >> 6;
        int k = r2 & 63;
        int c = half*64 + k;
        float w = (n < JOFF_) ? w_off[(n*CIN_ + c)*K_ + tap] : 0.f;
        __nv_bfloat16 hi = __float2bfloat16_rn(w);
        __nv_bfloat16 lo = __float2bfloat16_rn(w - __bfloat162float(hi));
        g_wobf[tap*8192 + half*4096 + n*64 + k]        = hi;
        g_wobf[tap*8192 + half*4096 + 2048 + n*64 + k] = lo;
    }
}

// ---------------------------------------------------------------------------
// Transpose concat(mem,que) -> channel-last g_xT[b][h][w][c=128].
// ---------------------------------------------------------------------------
__global__ __launch_bounds__(256) void transpose_x_kernel(
        const float* __restrict__ mem, const float* __restrict__ que) {
    __shared__ float tile[64][129];
    const int bh = blockIdx.x;
    const int b = bh >> 7, h = bh & 127;
    const int tid = threadIdx.x;
    #pragma unroll
    for (int pass = 0; pass < 2; pass++) {
        const float* src = (pass ? que + (size_t)b*CQ_*HW_ : mem + (size_t)b*CM_*HW_) + h*W_;
        #pragma unroll
        for (int m = 0; m < 32; m++) {
            int e = tid + 256*m;
            int c = e >> 7, w = e & 127;
            tile[c][w] = src[(size_t)c*HW_ + w];
        }
        __syncthreads();
        float* dst = g_xT + ((size_t)b*HW_ + h*W_)*CIN_ + pass*64;
        #pragma unroll
        for (int m = 0; m < 32; m++) {
            int e = tid + 256*m;
            int w = e >> 6, c = e & 63;
            dst[(size_t)w*CIN_ + c] = tile[c][w];
        }
        __syncthreads();
    }
}

// ---------------------------------------------------------------------------
// Offset conv on mma.sync (R12, proven): 18 stages, B LDGs before sync1,
// warp-private A staged between syncs, homogeneous warps.
// ---------------------------------------------------------------------------
__global__ __launch_bounds__(256, 3) void offset_mma_kernel(const float* __restrict__ b_off) {
    __shared__ __align__(16) char smem[40960];   // Ahi 16K | Alo 16K | Bhi 4K | Blo 4K
    char* Ahi = smem;
    char* Alo = smem + 16384;
    char* Bhi = smem + 32768;
    char* Blo = smem + 36864;
    const uint32_t ahi_u = smem_u32(Ahi), alo_u = smem_u32(Alo);
    const uint32_t bhi_u = smem_u32(Bhi), blo_u = smem_u32(Blo);

    const int tid  = threadIdx.x;
    const int lane = tid & 31;
    const int wrp  = tid >> 5;
    const int bh   = blockIdx.x;
    const int b    = bh >> 7;
    const int h    = bh & 127;
    const int wbase = wrp * 16;
    const int chunk = lane & 15;

    const char* xTb = (const char*)(g_xT + (size_t)b*HW_*CIN_);

    float C[4][4];
    #pragma unroll
    for (int nt = 0; nt < 4; nt++)
        #pragma unroll
        for (int i = 0; i < 4; i++) C[nt][i] = 0.f;

    for (int st = 0; st < 18; st++) {
        const int tap = st >> 1;
        const int hh  = st & 1;             // channel half
        const int ky  = tap / 3, kx = tap - ky*3;
        const int rowv = h + ky - 1;
        const bool rowok = (rowv >= 0 && rowv < H_);

        // ---- B LDGs early (fly under previous MMA drain) ----
        const uint4* bsrc = (const uint4*)(g_wobf + (size_t)tap*8192 + hh*4096);
        uint4 vh = bsrc[tid];
        uint4 vl = bsrc[256 + tid];

        __syncthreads();   // previous stage's MMAs done; smem writable

        // ---- STS B (swizzled) ----
        {
            int n = tid >> 3, kc = tid & 7;
            uint32_t doff = n*128 + ((kc ^ (n & 7)) << 4);
            *(uint4*)(Bhi + doff) = vh;
            *(uint4*)(Blo + doff) = vl;
        }

        // ---- stage A: shifted contiguous copy, bf16 hi/lo (warp-private) ----
        {
            const char* xrow = xTb + ((size_t)rowv*W_)*512 + hh*256;
            #pragma unroll
            for (int i = 0; i < 8; i++) {
                const int sub = 2*i + (lane >> 4);
                const int px  = wbase + sub;
                const int ww  = px + kx - 1;
                float4 v = make_float4(0.f, 0.f, 0.f, 0.f);
                if (rowok && ww >= 0 && ww < W_)
                    v = *(const float4*)(xrow + (size_t)ww*512 + chunk*16);
                uint16_t h0,h1,h2,h3,l0,l1,l2,l3;
                bf16split(v.x, h0, l0);
                bf16split(v.y, h1, l1);
                bf16split(v.z, h2, l2);
                bf16split(v.w, h3, l3);
                u64 hiq = ((u64)h3 << 48) | ((u64)h2 << 32) | ((u64)h1 << 16) | h0;
                u64 loq = ((u64)l3 << 48) | ((u64)l2 << 32) | ((u64)l1 << 16) | l0;
                const uint32_t off = SWB(px, chunk*8);
                *(u64*)(Ahi + off) = hiq;
                *(u64*)(Alo + off) = loq;
            }
        }
        __syncthreads();   // B visible everywhere; own A done

        // ---- MMA: 4 k-steps x 4 n-tiles x 3 split terms ----
        {
            const int arow = wbase + (lane & 15);
            const int acolh = ((lane >> 4) & 1) * 16;
            const int brow_base = lane & 7;
            const int bcolh = ((lane >> 3) & 1) * 16;
            #pragma unroll
            for (int ks = 0; ks < 4; ks++) {
                uint32_t Afh[4], Afl[4];
                uint32_t aoff = SWB(arow, ks*32 + acolh);
                ldsm_x4(Afh, ahi_u + aoff);
                ldsm_x4(Afl, alo_u + aoff);
                #pragma unroll
                for (int nt = 0; nt < 4; nt++) {
                    const int brow = nt*8 + brow_base;
                    uint32_t boff = SWB(brow, ks*32 + bcolh);
                    uint32_t Bfh[2], Bfl[2];
                    ldsm_x2(Bfh, bhi_u + boff);
                    ldsm_x2(Bfl, blo_u + boff);
                    mma16816(C[nt], Afh, Bfh);
                    mma16816(C[nt], Afl, Bfh);
                    mma16816(C[nt], Afh, Bfl);
                }
            }
        }
    }

    // ---- epilogue: C + bias -> g_off[b][j][h][w], j < 27 ----
    {
        const int g = lane >> 2, t4 = lane & 3;
        const int m0 = wbase + g;
        float* ob = g_off + (size_t)b*JOFF_*HW_ + h*W_;
        #pragma unroll
        for (int nt = 0; nt < 4; nt++) {
            const int n0 = nt*8 + 2*t4;
            if (n0 < JOFF_) {
                float bi = b_off[n0];
                ob[(size_t)n0*HW_ + m0]     = C[nt][0] + bi;
                ob[(size_t)n0*HW_ + m0 + 8] = C[nt][2] + bi;
            }
            if (n0 + 1 < JOFF_) {
                float bi = b_off[n0 + 1];
                ob[(size_t)(n0+1)*HW_ + m0]     = C[nt][1] + bi;
                ob[(size_t)(n0+1)*HW_ + m0 + 8] = C[nt][3] + bi;
            }
        }
    }
}

// ---------------------------------------------------------------------------
// Deformable conv (R12 shell + warp-pair N-split): homogeneous warps, params
// + B LDGs before sync1, gather between syncs. Warp pair (2w,2w+1) shares
// 32 A-rows; each warp computes one 32-wide N half -> ldsmB traffic halved.
// ---------------------------------------------------------------------------
__global__ __launch_bounds__(256, 3) void deform_mma_kernel(float* __restrict__ out) {
    __shared__ __align__(16) char smem[49152];   // Ahi 16K | Alo 16K | Bhi 8K | Blo 8K
    char* Ahi = smem;
    char* Alo = smem + 16384;
    char* Bhi = smem + 32768;
    char* Blo = smem + 40960;
    const uint32_t ahi_u = smem_u32(Ahi), alo_u = smem_u32(Alo);
    const uint32_t bhi_u = smem_u32(Bhi), blo_u = smem_u32(Blo);

    const int tid  = threadIdx.x;
    const int lane = tid & 31;
    const int wrp  = tid >> 5;
    const int bh   = blockIdx.x;
    const int b    = bh >> 7;
    const int h    = bh & 127;
    const int wbase = wrp * 16;          // gather rows (warp-private, as R12)
    const int chunk = lane & 15;

    const char* memTb = (const char*)(g_xT + (size_t)b*HW_*CIN_);  // ch 0-63 = mem
    const float* offrow = g_off + (size_t)b*JOFF_*HW_ + h*W_;

    float C[2][4][4];
    #pragma unroll
    for (int mt = 0; mt < 2; mt++)
        #pragma unroll
        for (int nt = 0; nt < 4; nt++)
            #pragma unroll
            for (int i = 0; i < 4; i++) C[mt][nt][i] = 0.f;

    for (int tap = 0; tap < K_; tap++) {
        // ---- per-warp bilinear params (LDGs fly under prev MMA) ----
        float W00, W01, W10, W11;
        int   B00, B01, B10, B11;
        {
            const int ppx = wbase + (lane & 15);
            const float* op = offrow + ppx;
            float dy  = op[(2*tap)*HW_];
            float dx  = op[(2*tap+1)*HW_];
            float msk = op[(18+tap)*HW_];
            float py  = (float)(h + (tap/3) - 1) + dy;
            float pxx = (float)(ppx + (tap - (tap/3)*3) - 1) + dx;
            float y0f = floorf(py), x0f = floorf(pxx);
            float fy = py - y0f, fx = pxx - x0f;
            int y0 = (int)y0f, x0 = (int)x0f;
            int y1 = y0 + 1,   x1 = x0 + 1;
            float vy0 = (y0 >= 0 && y0 < H_) ? 1.f : 0.f;
            float vy1 = (y1 >= 0 && y1 < H_) ? 1.f : 0.f;
            float vx0 = (x0 >= 0 && x0 < W_) ? 1.f : 0.f;
            float vx1 = (x1 >= 0 && x1 < W_) ? 1.f : 0.f;
            int y0c = min(max(y0, 0), H_-1), y1c = min(max(y1, 0), H_-1);
            int x0c = min(max(x0, 0), W_-1), x1c = min(max(x1, 0), W_-1);
            W00 = (1.f-fy)*(1.f-fx)*msk*vy0*vx0;
            W01 = (1.f-fy)*fx      *msk*vy0*vx1;
            W10 = fy      *(1.f-fx)*msk*vy1*vx0;
            W11 = fy      *fx      *msk*vy1*vx1;
            B00 = (y0c*W_ + x0c) << 9;    // *512B (128 ch x 4B per pixel)
            B01 = (y0c*W_ + x1c) << 9;
            B10 = (y1c*W_ + x0c) << 9;
            B11 = (y1c*W_ + x1c) << 9;
        }

        // ---- B LDGs early ----
        const uint4* bsrc = (const uint4*)(g_wbf + (size_t)tap*8192);
        uint4 bv[4];
        #pragma unroll
        for (int m = 0; m < 4; m++) bv[m] = bsrc[tid + 256*m];

        __syncthreads();   // previous tap's MMAs done; smem writable

        // ---- STS B (swizzled) ----
        #pragma unroll
        for (int m = 0; m < 4; m++) {
            int e = tid + 256*m;
            int e2 = e & 511;
            int n = e2 >> 3, kc = e2 & 7;
            char* dst = (e < 512) ? Bhi : Blo;
            *(uint4*)(dst + n*128 + ((kc ^ (n & 7)) << 4)) = bv[m];
        }

        // ---- gather: 8 iters x 2 pixels; lane = 16B channel chunk ----
        #pragma unroll
        for (int i = 0; i < 8; i++) {
            const int sub = 2*i + (lane >> 4);
            float w00 = __shfl_sync(0xffffffffu, W00, sub);
            float w01 = __shfl_sync(0xffffffffu, W01, sub);
            float w10 = __shfl_sync(0xffffffffu, W10, sub);
            float w11 = __shfl_sync(0xffffffffu, W11, sub);
            int   b00 = __shfl_sync(0xffffffffu, B00, sub);
            int   b01 = __shfl_sync(0xffffffffu, B01, sub);
            int   b10 = __shfl_sync(0xffffffffu, B10, sub);
            int   b11 = __shfl_sync(0xffffffffu, B11, sub);
            const int cb = chunk * 16;
            float4 c00 = *(const float4*)(memTb + b00 + cb);
            float4 c01 = *(const float4*)(memTb + b01 + cb);
            float4 c10 = *(const float4*)(memTb + b10 + cb);
            float4 c11 = *(const float4*)(memTb + b11 + cb);
            float s0 = w00*c00.x + w01*c01.x + w10*c10.x + w11*c11.x;
            float s1 = w00*c00.y + w01*c01.y + w10*c10.y + w11*c11.y;
            float s2 = w00*c00.z + w01*c01.z + w10*c10.z + w11*c11.z;
            float s3 = w00*c00.w + w01*c01.w + w10*c10.w + w11*c11.w;
            uint16_t h0,h1,h2,h3,l0,l1,l2,l3;
            bf16split(s0, h0, l0);
            bf16split(s1, h1, l1);
            bf16split(s2, h2, l2);
            bf16split(s3, h3, l3);
            u64 hiq = ((u64)h3 << 48) | ((u64)h2 << 32) | ((u64)h1 << 16) | h0;
            u64 loq = ((u64)l3 << 48) | ((u64)l2 << 32) | ((u64)l1 << 16) | l0;
            const int px = wbase + sub;
            const uint32_t off = SWB(px, chunk*8);
            *(u64*)(Ahi + off) = hiq;
            *(u64*)(Alo + off) = loq;
        }

        __syncthreads();   // B + all A tiles visible everywhere

        // ---- MMA: warp pair shares 32 rows; this warp does one N-half ----
        {
            const int arow0 = 32*(wrp >> 1) + (lane & 15);
            const int arow1 = arow0 + 16;
            const int nbase = (wrp & 1) * 32;
            const int acolh = ((lane >> 4) & 1) * 16;
            const int brow_base = lane & 7;
            const int bcolh = ((lane >> 3) & 1) * 16;
            #pragma unroll
            for (int ks = 0; ks < 4; ks++) {
                uint32_t Ah0[4], Al0[4], Ah1[4], Al1[4];
                uint32_t a0 = SWB(arow0, ks*32 + acolh);
                uint32_t a1 = SWB(arow1, ks*32 + acolh);
                ldsm_x4(Ah0, ahi_u + a0);
                ldsm_x4(Al0, alo_u + a0);
                ldsm_x4(Ah1, ahi_u + a1);
                ldsm_x4(Al1, alo_u + a1);
                #pragma unroll
                for (int nt = 0; nt < 4; nt++) {
                    const int brow = nbase + nt*8 + brow_base;
                    uint32_t boff = SWB(brow, ks*32 + bcolh);
                    uint32_t Bh[2], Bl[2];
                    ldsm_x2(Bh, bhi_u + boff);
                    ldsm_x2(Bl, blo_u + boff);
                    mma16816(C[0][nt], Ah0, Bh);
                    mma16816(C[0][nt], Al0, Bh);
                    mma16816(C[0][nt], Ah0, Bl);
                    mma16816(C[1][nt], Ah1, Bh);
                    mma16816(C[1][nt], Al1, Bh);
                    mma16816(C[1][nt], Ah1, Bl);
                }
            }
        }
    }

    // ---- epilogue: C fragment -> out[b][o][h][w] ----
    {
        const int g = lane >> 2, t4 = lane & 3;
        float* ob = out + (size_t)b*CO_*HW_ + h*W_;
        #pragma unroll
        for (int mt = 0; mt < 2; mt++) {
            const int m0 = 32*(wrp >> 1) + mt*16 + g;
            #pragma unroll
            for (int nt = 0; nt < 4; nt++) {
                const int n0 = (wrp & 1)*32 + nt*8 + 2*t4;
                ob[(size_t)n0*HW_ + m0]         = C[mt][nt][0];
                ob[(size_t)(n0+1)*HW_ + m0]     = C[mt][nt][1];
                ob[(size_t)n0*HW_ + m0 + 8]     = C[mt][nt][2];
                ob[(size_t)(n0+1)*HW_ + m0 + 8] = C[mt][nt][3];
            }
        }
    }
}

extern "C" void kernel_launch(void* const* d_in, const int* in_sizes, int n_in,
                              void* d_out, int out_size) {
    const float* mem   = (const float*)d_in[0];
    const float* que   = (const float*)d_in[1];
    const float* w_off = (const float*)d_in[2];
    const float* b_off = (const float*)d_in[3];
    const float* w_def = (const float*)d_in[4];
    float* out = (float*)d_out;

    prep_weights_kernel<<<(N_WB + N_WO + 255)/256, 256>>>(w_off, w_def);
    transpose_x_kernel<<<B_*H_, 256>>>(mem, que);
    offset_mma_kernel<<<B_*H_, 256>>>(b_off);
    deform_mma_kernel<<<B_*H_, 256>>>(out);
}

// round 15
// speedup vs baseline: 1.4262x; 1.1772x over previous
#include <cuda_runtime.h>
#include <cuda_bf16.h>
#include <cstdint>

typedef unsigned long long u64;

#define B_    8
#define CM_   64
#define CQ_   64
#define CIN_  128
#define CO_   64
#define H_    128
#define W_    128
#define K_    9
#define JOFF_ 27
#define HW_   (H_*W_)

// Scratch (no cudaMalloc allowed).
__device__ __align__(16) float  g_off[B_*JOFF_*HW_];      // [b][j][h][w]
__device__ __align__(16) __nv_bfloat16 g_wbf[K_*2*4096];  // deform W: [tap][hi|lo][n][k]
__device__ __align__(16) __nv_bfloat16 g_wobf[K_*2*2*2048]; // offset W: [tap][half][hi|lo][n=32][k=64]
__device__ __align__(16) float  g_xT[B_*HW_*CIN_];        // channel-last concat [b][h][w][c=128]

__device__ __forceinline__ uint32_t smem_u32(const void* p) {
    uint32_t a;
    asm("{ .reg .u64 t; cvta.to.shared.u64 t, %1; cvt.u32.u64 %0, t; }" : "=r"(a) : "l"(p));
    return a;
}

#define SWB(row, colb) ((row)*128 + ((((colb) >> 4) ^ ((row) & 7)) << 4) + ((colb) & 15))

__device__ __forceinline__ void ldsm_x4(uint32_t a[4], uint32_t addr) {
    asm volatile("ldmatrix.sync.aligned.m8n8.x4.shared.b16 {%0,%1,%2,%3}, [%4];"
        : "=r"(a[0]), "=r"(a[1]), "=r"(a[2]), "=r"(a[3]) : "r"(addr));
}
__device__ __forceinline__ void ldsm_x2(uint32_t b[2], uint32_t addr) {
    asm volatile("ldmatrix.sync.aligned.m8n8.x2.shared.b16 {%0,%1}, [%2];"
        : "=r"(b[0]), "=r"(b[1]) : "r"(addr));
}
__device__ __forceinline__ void mma16816(float c[4], const uint32_t a[4], const uint32_t b[2]) {
    asm volatile("mma.sync.aligned.m16n8k16.row.col.f32.bf16.bf16.f32 "
        "{%0,%1,%2,%3}, {%4,%5,%6,%7}, {%8,%9}, {%0,%1,%2,%3};"
        : "+f"(c[0]), "+f"(c[1]), "+f"(c[2]), "+f"(c[3])
        : "r"(a[0]), "r"(a[1]), "r"(a[2]), "r"(a[3]), "r"(b[0]), "r"(b[1]));
}

// split fp32 -> bf16 hi + residual lo
__device__ __forceinline__ void bf16split(float s, uint16_t &hi, uint16_t &lo) {
    __nv_bfloat16 h = __float2bfloat16_rn(s);
    __nv_bfloat16 l = __float2bfloat16_rn(s - __bfloat162float(h));
    hi = __bfloat16_as_ushort(h);
    lo = __bfloat16_as_ushort(l);
}

// ---------------------------------------------------------------------------
// Prep: deform weights (bf16 hi/lo [n][k]) + offset weights
// ([tap][half][hi|lo][n=32 pad][k=64]).
// ---------------------------------------------------------------------------
#define N_WB   (K_*64*64)       // 36864
#define N_WO   (K_*2*32*64)     // 36864
__global__ void prep_weights_kernel(const float* __restrict__ w_off,
                                    const float* __restrict__ w_def) {
    int i = blockIdx.x * 256 + threadIdx.x;
    if (i < N_WB) {
        int tap = i / 4096;
        int r = i - tap*4096;
        int n = r >> 6;
        int c = r & 63;
        float w = w_def[(n*CM_ + c)*K_ + tap];
        __nv_bfloat16 hi = __float2bfloat16_rn(w);
        __nv_bfloat16 lo = __float2bfloat16_rn(w - __bfloat162float(hi));
        g_wbf[tap*8192 + n*64 + c]        = hi;
        g_wbf[tap*8192 + 4096 + n*64 + c] = lo;
    } else if (i < N_WB + N_WO) {
        int i2 = i - N_WB;
        int tap = i2 / 4096;
        int r = i2 - tap*4096;
        int half = r >> 11;
        int r2 = r & 2047;
        int n = r2 >> 6;
        int k = r2 & 63;
        int c = half*64 + k;
        float w = (n < JOFF_) ? w_off[(n*CIN_ + c)*K_ + tap] : 0.f;
        __nv_bfloat16 hi = __float2bfloat16_rn(w);
        __nv_bfloat16 lo = __float2bfloat16_rn(w - __bfloat162float(hi));
        g_wobf[tap*8192 + half*4096 + n*64 + k]        = hi;
        g_wobf[tap*8192 + half*4096 + 2048 + n*64 + k] = lo;
    }
}

// ---------------------------------------------------------------------------
// Transpose concat(mem,que) -> channel-last g_xT[b][h][w][c=128].
// ---------------------------------------------------------------------------
__global__ __launch_bounds__(256) void transpose_x_kernel(
        const float* __restrict__ mem, const float* __restrict__ que) {
    __shared__ float tile[64][129];
    const int bh = blockIdx.x;
    const int b = bh >> 7, h = bh & 127;
    const int tid = threadIdx.x;
    #pragma unroll
    for (int pass = 0; pass < 2; pass++) {
        const float* src = (pass ? que + (size_t)b*CQ_*HW_ : mem + (size_t)b*CM_*HW_) + h*W_;
        #pragma unroll
        for (int m = 0; m < 32; m++) {
            int e = tid + 256*m;
            int c = e >> 7, w = e & 127;
            tile[c][w] = src[(size_t)c*HW_ + w];
        }
        __syncthreads();
        float* dst = g_xT + ((size_t)b*HW_ + h*W_)*CIN_ + pass*64;
        #pragma unroll
        for (int m = 0; m < 32; m++) {
            int e = tid + 256*m;
            int w = e >> 6, c = e & 63;
            dst[(size_t)w*CIN_ + c] = tile[c][w];
        }
        __syncthreads();
    }
}

// ---------------------------------------------------------------------------
// Offset conv on mma.sync, halo-A design: 6 stages (3 ky x 2 channel-halves).
// A staged ONCE per stage as a 130-row halo tile (pixel p -> row p+1, zero
// borders); the 3 kx shifts are free via ldsm row addressing (row px+kx).
// B for all 3 taps of this ky prefetched before sync1. MMA/ldsm counts
// identical to R12; gather/cvt/STS cut 3x. Smem 57.9KB dynamic.
// ---------------------------------------------------------------------------
#define OA_BYTES   16640                  // 130 rows x 128B
#define OB_BASE    (2*OA_BYTES)           // 33280
#define OSM_BYTES  (OB_BASE + 3*8192)     // 57856

__global__ __launch_bounds__(256, 3) void offset_mma_kernel(const float* __restrict__ b_off) {
    extern __shared__ __align__(16) char smem[];
    char* Ahi = smem;
    char* Alo = smem + OA_BYTES;
    const uint32_t ahi_u = smem_u32(Ahi), alo_u = smem_u32(Alo);
    const uint32_t bb_u  = smem_u32(smem + OB_BASE);

    const int tid  = threadIdx.x;
    const int lane = tid & 31;
    const int wrp  = tid >> 5;
    const int bh   = blockIdx.x;
    const int b    = bh >> 7;
    const int h    = bh & 127;
    const int wbase = wrp * 16;

    const char* xTb = (const char*)(g_xT + (size_t)b*HW_*CIN_);

    float C[4][4];
    #pragma unroll
    for (int nt = 0; nt < 4; nt++)
        #pragma unroll
        for (int i = 0; i < 4; i++) C[nt][i] = 0.f;

    #pragma unroll
    for (int st = 0; st < 6; st++) {
        const int ky = st >> 1;
        const int hh = st & 1;              // channel half
        const int rowv = h + ky - 1;
        const bool rowok = (rowv >= 0 && rowv < H_);

        // ---- prefetch B for 3 taps of this ky (fly under previous MMA) ----
        uint4 bv[6];
        #pragma unroll
        for (int m = 0; m < 6; m++) {
            int e = tid + 256*m;            // 0..1535
            int kx = e >> 9;                // 512 uint4 per tap
            bv[m] = ((const uint4*)(g_wobf + (size_t)(ky*3 + kx)*8192 + hh*4096))[e & 511];
        }

        __syncthreads();   // previous stage's MMAs done; smem writable

        // ---- STS B (swizzled), 3 taps ----
        #pragma unroll
        for (int m = 0; m < 6; m++) {
            int e = tid + 256*m;
            int kx = e >> 9;
            int e2 = e & 511;
            int n = (e2 & 255) >> 3, kc = e2 & 7;
            char* dst = smem + OB_BASE + kx*8192 + ((e2 < 256) ? 0 : 4096);
            *(uint4*)(dst + n*128 + ((kc ^ (n & 7)) << 4)) = bv[m];
        }

        // ---- stage A halo tile: rows 0..129, row r = pixel r-1 ----
        {
            const char* xrow = xTb + ((size_t)rowv*W_)*512 + hh*256;
            const int chunk = tid & 15;
            #pragma unroll
            for (int it = 0; it < 9; it++) {
                const int r = (tid >> 4) + 16*it;
                if (r < 130) {
                    const int p = r - 1;
                    float4 v = make_float4(0.f, 0.f, 0.f, 0.f);
                    if (rowok && p >= 0 && p < W_)
                        v = *(const float4*)(xrow + (size_t)p*512 + chunk*16);
                    uint16_t h0,h1,h2,h3,l0,l1,l2,l3;
                    bf16split(v.x, h0, l0);
                    bf16split(v.y, h1, l1);
                    bf16split(v.z, h2, l2);
                    bf16split(v.w, h3, l3);
                    u64 hiq = ((u64)h3 << 48) | ((u64)h2 << 32) | ((u64)h1 << 16) | h0;
                    u64 loq = ((u64)l3 << 48) | ((u64)l2 << 32) | ((u64)l1 << 16) | l0;
                    const uint32_t off = SWB(r, chunk*8);
                    *(u64*)(Ahi + off) = hiq;
                    *(u64*)(Alo + off) = loq;
                }
            }
        }
        __syncthreads();   // A + B ready everywhere

        // ---- MMA: 3 kx passes x 4 k-steps x 4 n-tiles x 3 split terms ----
        {
            const int acolh = ((lane >> 4) & 1) * 16;
            const int brow_base = lane & 7;
            const int bcolh = ((lane >> 3) & 1) * 16;
            #pragma unroll
            for (int kx = 0; kx < 3; kx++) {
                const int arow = wbase + (lane & 15) + kx;   // pixel px+kx-1
                const uint32_t bhi_u = bb_u + kx*8192;
                const uint32_t blo_u = bhi_u + 4096;
                #pragma unroll
                for (int ks = 0; ks < 4; ks++) {
                    uint32_t Afh[4], Afl[4];
                    uint32_t aoff = SWB(arow, ks*32 + acolh);
                    ldsm_x4(Afh, ahi_u + aoff);
                    ldsm_x4(Afl, alo_u + aoff);
                    #pragma unroll
                    for (int nt = 0; nt < 4; nt++) {
                        const int brow = nt*8 + brow_base;
                        uint32_t boff = SWB(brow, ks*32 + bcolh);
                        uint32_t Bfh[2], Bfl[2];
                        ldsm_x2(Bfh, bhi_u + boff);
                        ldsm_x2(Bfl, blo_u + boff);
                        mma16816(C[nt], Afh, Bfh);
                        mma16816(C[nt], Afl, Bfh);
                        mma16816(C[nt], Afh, Bfl);
                    }
                }
            }
        }
    }

    // ---- epilogue: C + bias -> g_off[b][j][h][w], j < 27 ----
    {
        const int g = lane >> 2, t4 = lane & 3;
        const int m0 = wbase + g;
        float* ob = g_off + (size_t)b*JOFF_*HW_ + h*W_;
        #pragma unroll
        for (int nt = 0; nt < 4; nt++) {
            const int n0 = nt*8 + 2*t4;
            if (n0 < JOFF_) {
                float bi = b_off[n0];
                ob[(size_t)n0*HW_ + m0]     = C[nt][0] + bi;
                ob[(size_t)n0*HW_ + m0 + 8] = C[nt][2] + bi;
            }
            if (n0 + 1 < JOFF_) {
                float bi = b_off[n0 + 1];
                ob[(size_t)(n0+1)*HW_ + m0]     = C[nt][1] + bi;
                ob[(size_t)(n0+1)*HW_ + m0 + 8] = C[nt][3] + bi;
            }
        }
    }
}

// ---------------------------------------------------------------------------
// Deformable conv (EXACT R12, frozen): homogeneous warps, params + B LDGs
// before sync1, gather between syncs, M=16/warp, N=64.
// ---------------------------------------------------------------------------
__global__ __launch_bounds__(256, 3) void deform_mma_kernel(float* __restrict__ out) {
    __shared__ __align__(16) char smem[49152];   // Ahi 16K | Alo 16K | Bhi 8K | Blo 8K
    char* Ahi = smem;
    char* Alo = smem + 16384;
    char* Bhi = smem + 32768;
    char* Blo = smem + 40960;
    const uint32_t ahi_u = smem_u32(Ahi), alo_u = smem_u32(Alo);
    const uint32_t bhi_u = smem_u32(Bhi), blo_u = smem_u32(Blo);

    const int tid  = threadIdx.x;
    const int lane = tid & 31;
    const int wrp  = tid >> 5;
    const int bh   = blockIdx.x;
    const int b    = bh >> 7;
    const int h    = bh & 127;
    const int wbase = wrp * 16;
    const int chunk = lane & 15;

    const char* memTb = (const char*)(g_xT + (size_t)b*HW_*CIN_);  // ch 0-63 = mem
    const float* offrow = g_off + (size_t)b*JOFF_*HW_ + h*W_;

    float C[8][4];
    #pragma unroll
    for (int nt = 0; nt < 8; nt++)
        #pragma unroll
        for (int i = 0; i < 4; i++) C[nt][i] = 0.f;

    for (int tap = 0; tap < K_; tap++) {
        // ---- per-warp bilinear params (no smem; LDGs fly under prev MMA) ----
        float W00, W01, W10, W11;
        int   B00, B01, B10, B11;
        {
            const int ppx = wbase + (lane & 15);
            const float* op = offrow + ppx;
            float dy  = op[(2*tap)*HW_];
            float dx  = op[(2*tap+1)*HW_];
            float msk = op[(18+tap)*HW_];
            float py  = (float)(h + (tap/3) - 1) + dy;
            float pxx = (float)(ppx + (tap - (tap/3)*3) - 1) + dx;
            float y0f = floorf(py), x0f = floorf(pxx);
            float fy = py - y0f, fx = pxx - x0f;
            int y0 = (int)y0f, x0 = (int)x0f;
            int y1 = y0 + 1,   x1 = x0 + 1;
            float vy0 = (y0 >= 0 && y0 < H_) ? 1.f : 0.f;
            float vy1 = (y1 >= 0 && y1 < H_) ? 1.f : 0.f;
            float vx0 = (x0 >= 0 && x0 < W_) ? 1.f : 0.f;
            float vx1 = (x1 >= 0 && x1 < W_) ? 1.f : 0.f;
            int y0c = min(max(y0, 0), H_-1), y1c = min(max(y1, 0), H_-1);
            int x0c = min(max(x0, 0), W_-1), x1c = min(max(x1, 0), W_-1);
            W00 = (1.f-fy)*(1.f-fx)*msk*vy0*vx0;
            W01 = (1.f-fy)*fx      *msk*vy0*vx1;
            W10 = fy      *(1.f-fx)*msk*vy1*vx0;
            W11 = fy      *fx      *msk*vy1*vx1;
            B00 = (y0c*W_ + x0c) << 9;    // *512B (128 ch x 4B per pixel)
            B01 = (y0c*W_ + x1c) << 9;
            B10 = (y1c*W_ + x0c) << 9;
            B11 = (y1c*W_ + x1c) << 9;
        }

        // ---- B LDGs early ----
        const uint4* bsrc = (const uint4*)(g_wbf + (size_t)tap*8192);
        uint4 bv[4];
        #pragma unroll
        for (int m = 0; m < 4; m++) bv[m] = bsrc[tid + 256*m];

        __syncthreads();   // previous tap's MMAs done; smem writable

        // ---- STS B (swizzled) ----
        #pragma unroll
        for (int m = 0; m < 4; m++) {
            int e = tid + 256*m;
            int e2 = e & 511;
            int n = e2 >> 3, kc = e2 & 7;
            char* dst = (e < 512) ? Bhi : Blo;
            *(uint4*)(dst + n*128 + ((kc ^ (n & 7)) << 4)) = bv[m];
        }

        // ---- gather: 8 iters x 2 pixels; lane = 16B channel chunk ----
        #pragma unroll
        for (int i = 0; i < 8; i++) {
            const int sub = 2*i + (lane >> 4);
            float w00 = __shfl_sync(0xffffffffu, W00, sub);
            float w01 = __shfl_sync(0xffffffffu, W01, sub);
            float w10 = __shfl_sync(0xffffffffu, W10, sub);
            float w11 = __shfl_sync(0xffffffffu, W11, sub);
            int   b00 = __shfl_sync(0xffffffffu, B00, sub);
            int   b01 = __shfl_sync(0xffffffffu, B01, sub);
            int   b10 = __shfl_sync(0xffffffffu, B10, sub);
            int   b11 = __shfl_sync(0xffffffffu, B11, sub);
            const int cb = chunk * 16;
            float4 c00 = *(const float4*)(memTb + b00 + cb);
            float4 c01 = *(const float4*)(memTb + b01 + cb);
            float4 c10 = *(const float4*)(memTb + b10 + cb);
            float4 c11 = *(const float4*)(memTb + b11 + cb);
            float s0 = w00*c00.x + w01*c01.x + w10*c10.x + w11*c11.x;
            float s1 = w00*c00.y + w01*c01.y + w10*c10.y + w11*c11.y;
            float s2 = w00*c00.z + w01*c01.z + w10*c10.z + w11*c11.z;
            float s3 = w00*c00.w + w01*c01.w + w10*c10.w + w11*c11.w;
            uint16_t h0,h1,h2,h3,l0,l1,l2,l3;
            bf16split(s0, h0, l0);
            bf16split(s1, h1, l1);
            bf16split(s2, h2, l2);
            bf16split(s3, h3, l3);
            u64 hiq = ((u64)h3 << 48) | ((u64)h2 << 32) | ((u64)h1 << 16) | h0;
            u64 loq = ((u64)l3 << 48) | ((u64)l2 << 32) | ((u64)l1 << 16) | l0;
            const int px = wbase + sub;
            const uint32_t off = SWB(px, chunk*8);
            *(u64*)(Ahi + off) = hiq;
            *(u64*)(Alo + off) = loq;
        }

        __syncthreads();   // B visible everywhere; own A done (warp-private)

        // ---- MMA: 4 k-steps x 8 n-tiles x 3 split terms ----
        {
            const int arow = wbase + (lane & 15);
            const int acolh = ((lane >> 4) & 1) * 16;
            const int brow_base = lane & 7;
            const int bcolh = ((lane >> 3) & 1) * 16;
            #pragma unroll
            for (int ks = 0; ks < 4; ks++) {
                uint32_t Afh[4], Afl[4];
                uint32_t aoff = SWB(arow, ks*32 + acolh);
                ldsm_x4(Afh, ahi_u + aoff);
                ldsm_x4(Afl, alo_u + aoff);
                #pragma unroll
                for (int nt = 0; nt < 8; nt++) {
                    const int brow = nt*8 + brow_base;
                    uint32_t boff = SWB(brow, ks*32 + bcolh);
                    uint32_t Bfh[2], Bfl[2];
                    ldsm_x2(Bfh, bhi_u + boff);
                    ldsm_x2(Bfl, blo_u + boff);
                    mma16816(C[nt], Afh, Bfh);
                    mma16816(C[nt], Afl, Bfh);
                    mma16816(C[nt], Afh, Bfl);
                }
            }
        }
    }

    // ---- epilogue: C fragment -> out[b][o][h][w] ----
    {
        const int g = lane >> 2, t = lane & 3;
        const int m0 = wbase + g;
        float* ob = out + (size_t)b*CO_*HW_ + h*W_;
        #pragma unroll
        for (int nt = 0; nt < 8; nt++) {
            const int n0 = nt*8 + 2*t;
            ob[(size_t)n0*HW_ + m0]         = C[nt][0];
            ob[(size_t)(n0+1)*HW_ + m0]     = C[nt][1];
            ob[(size_t)n0*HW_ + m0 + 8]     = C[nt][2];
            ob[(size_t)(n0+1)*HW_ + m0 + 8] = C[nt][3];
        }
    }
}

extern "C" void kernel_launch(void* const* d_in, const int* in_sizes, int n_in,
                              void* d_out, int out_size) {
    const float* mem   = (const float*)d_in[0];
    const float* que   = (const float*)d_in[1];
    const float* w_off = (const float*)d_in[2];
    const float* b_off = (const float*)d_in[3];
    const float* w_def = (const float*)d_in[4];
    float* out = (float*)d_out;

    cudaFuncSetAttribute(offset_mma_kernel,
                         cudaFuncAttributeMaxDynamicSharedMemorySize, OSM_BYTES);

    prep_weights_kernel<<<(N_WB + N_WO + 255)/256, 256>>>(w_off, w_def);
    transpose_x_kernel<<<B_*H_, 256>>>(mem, que);
    offset_mma_kernel<<<B_*H_, 256, OSM_BYTES>>>(b_off);
    deform_mma_kernel<<<B_*H_, 256>>>(out);
}

// round 16
// speedup vs baseline: 1.4635x; 1.0261x over previous
#include <cuda_runtime.h>
#include <cuda_bf16.h>
#include <cstdint>

typedef unsigned long long u64;

#define B_    8
#define CM_   64
#define CQ_   64
#define CIN_  128
#define CO_   64
#define H_    128
#define W_    128
#define K_    9
#define JOFF_ 27
#define HW_   (H_*W_)

// Scratch (no cudaMalloc allowed).
__device__ __align__(16) float  g_off[B_*JOFF_*HW_];      // [b][j][h][w]
__device__ __align__(16) __nv_bfloat16 g_wbf[K_*2*4096];  // deform W: [tap][hi|lo][n][k]
__device__ __align__(16) __nv_bfloat16 g_wobf[K_*2*2*2048]; // offset W: [tap][half][hi|lo][n=32][k=64]
__device__ __align__(16) float  g_xT[B_*HW_*CIN_];        // channel-last concat [b][h][w][c=128]

__device__ __forceinline__ uint32_t smem_u32(const void* p) {
    uint32_t a;
    asm("{ .reg .u64 t; cvta.to.shared.u64 t, %1; cvt.u32.u64 %0, t; }" : "=r"(a) : "l"(p));
    return a;
}

#define SWB(row, colb) ((row)*128 + ((((colb) >> 4) ^ ((row) & 7)) << 4) + ((colb) & 15))

__device__ __forceinline__ void ldsm_x4(uint32_t a[4], uint32_t addr) {
    asm volatile("ldmatrix.sync.aligned.m8n8.x4.shared.b16 {%0,%1,%2,%3}, [%4];"
        : "=r"(a[0]), "=r"(a[1]), "=r"(a[2]), "=r"(a[3]) : "r"(addr));
}
__device__ __forceinline__ void ldsm_x2(uint32_t b[2], uint32_t addr) {
    asm volatile("ldmatrix.sync.aligned.m8n8.x2.shared.b16 {%0,%1}, [%2];"
        : "=r"(b[0]), "=r"(b[1]) : "r"(addr));
}
__device__ __forceinline__ void mma16816(float c[4], const uint32_t a[4], const uint32_t b[2]) {
    asm volatile("mma.sync.aligned.m16n8k16.row.col.f32.bf16.bf16.f32 "
        "{%0,%1,%2,%3}, {%4,%5,%6,%7}, {%8,%9}, {%0,%1,%2,%3};"
        : "+f"(c[0]), "+f"(c[1]), "+f"(c[2]), "+f"(c[3])
        : "r"(a[0]), "r"(a[1]), "r"(a[2]), "r"(a[3]), "r"(b[0]), "r"(b[1]));
}

// scalar split (prep only)
__device__ __forceinline__ void bf16split(float s, uint16_t &hi, uint16_t &lo) {
    __nv_bfloat16 h = __float2bfloat16_rn(s);
    __nv_bfloat16 l = __float2bfloat16_rn(s - __bfloat162float(h));
    hi = __bfloat16_as_ushort(h);
    lo = __bfloat16_as_ushort(l);
}

// packed split: {s1,s0} -> hi2 = {bf16(s1),bf16(s0)}, lo2 = residual pair.
// Bit-identical to per-value __float2bfloat16_rn (both rn; hi reconstructed
// exactly via shift).
__device__ __forceinline__ void bf16split2(float s0, float s1,
                                           uint32_t &hi2, uint32_t &lo2) {
    asm("cvt.rn.bf16x2.f32 %0, %1, %2;" : "=r"(hi2) : "f"(s1), "f"(s0));
    float h0 = __uint_as_float(hi2 << 16);
    float h1 = __uint_as_float(hi2 & 0xffff0000u);
    asm("cvt.rn.bf16x2.f32 %0, %1, %2;" : "=r"(lo2) : "f"(s1 - h1), "f"(s0 - h0));
}

// ---------------------------------------------------------------------------
// Setup (one launch): blocks 0..1023 transpose concat(mem,que) -> g_xT;
// blocks 1024..1311 prep both weight tensors.
// ---------------------------------------------------------------------------
#define N_WB   (K_*64*64)       // 36864
#define N_WO   (K_*2*32*64)     // 36864
#define SETUP_BLOCKS (B_*H_ + (N_WB + N_WO + 255)/256)   // 1024 + 288

__global__ __launch_bounds__(256) void setup_kernel(
        const float* __restrict__ mem, const float* __restrict__ que,
        const float* __restrict__ w_off, const float* __restrict__ w_def) {
    __shared__ float tile[64][129];
    const int tid = threadIdx.x;
    if (blockIdx.x < B_*H_) {
        const int bh = blockIdx.x;
        const int b = bh >> 7, h = bh & 127;
        #pragma unroll
        for (int pass = 0; pass < 2; pass++) {
            const float* src = (pass ? que + (size_t)b*CQ_*HW_ : mem + (size_t)b*CM_*HW_) + h*W_;
            #pragma unroll
            for (int m = 0; m < 32; m++) {
                int e = tid + 256*m;
                int c = e >> 7, w = e & 127;
                tile[c][w] = src[(size_t)c*HW_ + w];
            }
            __syncthreads();
            float* dst = g_xT + ((size_t)b*HW_ + h*W_)*CIN_ + pass*64;
            #pragma unroll
            for (int m = 0; m < 32; m++) {
                int e = tid + 256*m;
                int w = e >> 6, c = e & 63;
                dst[(size_t)w*CIN_ + c] = tile[c][w];
            }
            __syncthreads();
        }
    } else {
        int i = (blockIdx.x - B_*H_) * 256 + tid;
        if (i < N_WB) {
            int tap = i / 4096;
            int r = i - tap*4096;
            int n = r >> 6;
            int c = r & 63;
            float w = w_def[(n*CM_ + c)*K_ + tap];
            uint16_t hi, lo;
            bf16split(w, hi, lo);
            g_wbf[tap*8192 + n*64 + c]        = __ushort_as_bfloat16(hi);
            g_wbf[tap*8192 + 4096 + n*64 + c] = __ushort_as_bfloat16(lo);
        } else if (i < N_WB + N_WO) {
            int i2 = i - N_WB;
            int tap = i2 / 4096;
            int r = i2 - tap*4096;
            int half = r >> 11;
            int r2 = r & 2047;
            int n = r2 >> 6;
            int k = r2 & 63;
            int c = half*64 + k;
            float w = (n < JOFF_) ? w_off[(n*CIN_ + c)*K_ + tap] : 0.f;
            uint16_t hi, lo;
            bf16split(w, hi, lo);
            g_wobf[tap*8192 + half*4096 + n*64 + k]        = __ushort_as_bfloat16(hi);
            g_wobf[tap*8192 + half*4096 + 2048 + n*64 + k] = __ushort_as_bfloat16(lo);
        }
    }
}

// ---------------------------------------------------------------------------
// Offset conv on mma.sync, halo-A design (R15, frozen structure): 6 stages
// (3 ky x 2 channel-halves), A staged once per stage as 130-row halo tile,
// 3 kx shifts free via ldsm row addressing. Packed bf16 split in staging.
// ---------------------------------------------------------------------------
#define OA_BYTES   16640                  // 130 rows x 128B
#define OB_BASE    (2*OA_BYTES)           // 33280
#define OSM_BYTES  (OB_BASE + 3*8192)     // 57856

__global__ __launch_bounds__(256, 3) void offset_mma_kernel(const float* __restrict__ b_off) {
    extern __shared__ __align__(16) char smem[];
    char* Ahi = smem;
    char* Alo = smem + OA_BYTES;
    const uint32_t ahi_u = smem_u32(Ahi), alo_u = smem_u32(Alo);
    const uint32_t bb_u  = smem_u32(smem + OB_BASE);

    const int tid  = threadIdx.x;
    const int lane = tid & 31;
    const int wrp  = tid >> 5;
    const int bh   = blockIdx.x;
    const int b    = bh >> 7;
    const int h    = bh & 127;
    const int wbase = wrp * 16;

    const char* xTb = (const char*)(g_xT + (size_t)b*HW_*CIN_);

    float C[4][4];
    #pragma unroll
    for (int nt = 0; nt < 4; nt++)
        #pragma unroll
        for (int i = 0; i < 4; i++) C[nt][i] = 0.f;

    #pragma unroll
    for (int st = 0; st < 6; st++) {
        const int ky = st >> 1;
        const int hh = st & 1;              // channel half
        const int rowv = h + ky - 1;
        const bool rowok = (rowv >= 0 && rowv < H_);

        // ---- prefetch B for 3 taps of this ky (fly under previous MMA) ----
        uint4 bv[6];
        #pragma unroll
        for (int m = 0; m < 6; m++) {
            int e = tid + 256*m;            // 0..1535
            int kx = e >> 9;                // 512 uint4 per tap
            bv[m] = ((const uint4*)(g_wobf + (size_t)(ky*3 + kx)*8192 + hh*4096))[e & 511];
        }

        __syncthreads();   // previous stage's MMAs done; smem writable

        // ---- STS B (swizzled), 3 taps ----
        #pragma unroll
        for (int m = 0; m < 6; m++) {
            int e = tid + 256*m;
            int kx = e >> 9;
            int e2 = e & 511;
            int n = (e2 & 255) >> 3, kc = e2 & 7;
            char* dst = smem + OB_BASE + kx*8192 + ((e2 < 256) ? 0 : 4096);
            *(uint4*)(dst + n*128 + ((kc ^ (n & 7)) << 4)) = bv[m];
        }

        // ---- stage A halo tile: rows 0..129, row r = pixel r-1 ----
        {
            const char* xrow = xTb + ((size_t)rowv*W_)*512 + hh*256;
            const int chunk = tid & 15;
            #pragma unroll
            for (int it = 0; it < 9; it++) {
                const int r = (tid >> 4) + 16*it;
                if (r < 130) {
                    const int p = r - 1;
                    float4 v = make_float4(0.f, 0.f, 0.f, 0.f);
                    if (rowok && p >= 0 && p < W_)
                        v = *(const float4*)(xrow + (size_t)p*512 + chunk*16);
                    uint32_t hi01, lo01, hi23, lo23;
                    bf16split2(v.x, v.y, hi01, lo01);
                    bf16split2(v.z, v.w, hi23, lo23);
                    u64 hiq = ((u64)hi23 << 32) | hi01;
                    u64 loq = ((u64)lo23 << 32) | lo01;
                    const uint32_t off = SWB(r, chunk*8);
                    *(u64*)(Ahi + off) = hiq;
                    *(u64*)(Alo + off) = loq;
                }
            }
        }
        __syncthreads();   // A + B ready everywhere

        // ---- MMA: 3 kx passes x 4 k-steps x 4 n-tiles x 3 split terms ----
        {
            const int acolh = ((lane >> 4) & 1) * 16;
            const int brow_base = lane & 7;
            const int bcolh = ((lane >> 3) & 1) * 16;
            #pragma unroll
            for (int kx = 0; kx < 3; kx++) {
                const int arow = wbase + (lane & 15) + kx;   // pixel px+kx-1
                const uint32_t bhi_u = bb_u + kx*8192;
                const uint32_t blo_u = bhi_u + 4096;
                #pragma unroll
                for (int ks = 0; ks < 4; ks++) {
                    uint32_t Afh[4], Afl[4];
                    uint32_t aoff = SWB(arow, ks*32 + acolh);
                    ldsm_x4(Afh, ahi_u + aoff);
                    ldsm_x4(Afl, alo_u + aoff);
                    #pragma unroll
                    for (int nt = 0; nt < 4; nt++) {
                        const int brow = nt*8 + brow_base;
                        uint32_t boff = SWB(brow, ks*32 + bcolh);
                        uint32_t Bfh[2], Bfl[2];
                        ldsm_x2(Bfh, bhi_u + boff);
                        ldsm_x2(Bfl, blo_u + boff);
                        mma16816(C[nt], Afh, Bfh);
                        mma16816(C[nt], Afl, Bfh);
                        mma16816(C[nt], Afh, Bfl);
                    }
                }
            }
        }
    }

    // ---- epilogue: C + bias -> g_off[b][j][h][w], j < 27 ----
    {
        const int g = lane >> 2, t4 = lane & 3;
        const int m0 = wbase + g;
        float* ob = g_off + (size_t)b*JOFF_*HW_ + h*W_;
        #pragma unroll
        for (int nt = 0; nt < 4; nt++) {
            const int n0 = nt*8 + 2*t4;
            if (n0 < JOFF_) {
                float bi = b_off[n0];
                ob[(size_t)n0*HW_ + m0]     = C[nt][0] + bi;
                ob[(size_t)n0*HW_ + m0 + 8] = C[nt][2] + bi;
            }
            if (n0 + 1 < JOFF_) {
                float bi = b_off[n0 + 1];
                ob[(size_t)(n0+1)*HW_ + m0]     = C[nt][1] + bi;
                ob[(size_t)(n0+1)*HW_ + m0 + 8] = C[nt][3] + bi;
            }
        }
    }
}

// ---------------------------------------------------------------------------
// Deformable conv (R12 schedule, frozen): homogeneous warps, params + B LDGs
// before sync1, gather between syncs, M=16/warp, N=64. Packed bf16 split.
// ---------------------------------------------------------------------------
__global__ __launch_bounds__(256, 3) void deform_mma_kernel(float* __restrict__ out) {
    __shared__ __align__(16) char smem[49152];   // Ahi 16K | Alo 16K | Bhi 8K | Blo 8K
    char* Ahi = smem;
    char* Alo = smem + 16384;
    char* Bhi = smem + 32768;
    char* Blo = smem + 40960;
    const uint32_t ahi_u = smem_u32(Ahi), alo_u = smem_u32(Alo);
    const uint32_t bhi_u = smem_u32(Bhi), blo_u = smem_u32(Blo);

    const int tid  = threadIdx.x;
    const int lane = tid & 31;
    const int wrp  = tid >> 5;
    const int bh   = blockIdx.x;
    const int b    = bh >> 7;
    const int h    = bh & 127;
    const int wbase = wrp * 16;
    const int chunk = lane & 15;

    const char* memTb = (const char*)(g_xT + (size_t)b*HW_*CIN_);  // ch 0-63 = mem
    const float* offrow = g_off + (size_t)b*JOFF_*HW_ + h*W_;

    float C[8][4];
    #pragma unroll
    for (int nt = 0; nt < 8; nt++)
        #pragma unroll
        for (int i = 0; i < 4; i++) C[nt][i] = 0.f;

    for (int tap = 0; tap < K_; tap++) {
        // ---- per-warp bilinear params (no smem; LDGs fly under prev MMA) ----
        float W00, W01, W10, W11;
        int   B00, B01, B10, B11;
        {
            const int ppx = wbase + (lane & 15);
            const float* op = offrow + ppx;
            float dy  = op[(2*tap)*HW_];
            float dx  = op[(2*tap+1)*HW_];
            float msk = op[(18+tap)*HW_];
            float py  = (float)(h + (tap/3) - 1) + dy;
            float pxx = (float)(ppx + (tap - (tap/3)*3) - 1) + dx;
            float y0f = floorf(py), x0f = floorf(pxx);
            float fy = py - y0f, fx = pxx - x0f;
            int y0 = (int)y0f, x0 = (int)x0f;
            int y1 = y0 + 1,   x1 = x0 + 1;
            float vy0 = (y0 >= 0 && y0 < H_) ? 1.f : 0.f;
            float vy1 = (y1 >= 0 && y1 < H_) ? 1.f : 0.f;
            float vx0 = (x0 >= 0 && x0 < W_) ? 1.f : 0.f;
            float vx1 = (x1 >= 0 && x1 < W_) ? 1.f : 0.f;
            int y0c = min(max(y0, 0), H_-1), y1c = min(max(y1, 0), H_-1);
            int x0c = min(max(x0, 0), W_-1), x1c = min(max(x1, 0), W_-1);
            W00 = (1.f-fy)*(1.f-fx)*msk*vy0*vx0;
            W01 = (1.f-fy)*fx      *msk*vy0*vx1;
            W10 = fy      *(1.f-fx)*msk*vy1*vx0;
            W11 = fy      *fx      *msk*vy1*vx1;
            B00 = (y0c*W_ + x0c) << 9;    // *512B (128 ch x 4B per pixel)
            B01 = (y0c*W_ + x1c) << 9;
            B10 = (y1c*W_ + x0c) << 9;
            B11 = (y1c*W_ + x1c) << 9;
        }

        // ---- B LDGs early ----
        const uint4* bsrc = (const uint4*)(g_wbf + (size_t)tap*8192);
        uint4 bv[4];
        #pragma unroll
        for (int m = 0; m < 4; m++) bv[m] = bsrc[tid + 256*m];

        __syncthreads();   // previous tap's MMAs done; smem writable

        // ---- STS B (swizzled) ----
        #pragma unroll
        for (int m = 0; m < 4; m++) {
            int e = tid + 256*m;
            int e2 = e & 511;
            int n = e2 >> 3, kc = e2 & 7;
            char* dst = (e < 512) ? Bhi : Blo;
            *(uint4*)(dst + n*128 + ((kc ^ (n & 7)) << 4)) = bv[m];
        }

        // ---- gather: 8 iters x 2 pixels; lane = 16B channel chunk ----
        #pragma unroll
        for (int i = 0; i < 8; i++) {
            const int sub = 2*i + (lane >> 4);
            float w00 = __shfl_sync(0xffffffffu, W00, sub);
            float w01 = __shfl_sync(0xffffffffu, W01, sub);
            float w10 = __shfl_sync(0xffffffffu, W10, sub);
            float w11 = __shfl_sync(0xffffffffu, W11, sub);
            int   b00 = __shfl_sync(0xffffffffu, B00, sub);
            int   b01 = __shfl_sync(0xffffffffu, B01, sub);
            int   b10 = __shfl_sync(0xffffffffu, B10, sub);
            int   b11 = __shfl_sync(0xffffffffu, B11, sub);
            const int cb = chunk * 16;
            float4 c00 = *(const float4*)(memTb + b00 + cb);
            float4 c01 = *(const float4*)(memTb + b01 + cb);
            float4 c10 = *(const float4*)(memTb + b10 + cb);
            float4 c11 = *(const float4*)(memTb + b11 + cb);
            float s0 = w00*c00.x + w01*c01.x + w10*c10.x + w11*c11.x;
            float s1 = w00*c00.y + w01*c01.y + w10*c10.y + w11*c11.y;
            float s2 = w00*c00.z + w01*c01.z + w10*c10.z + w11*c11.z;
            float s3 = w00*c00.w + w01*c01.w + w10*c10.w + w11*c11.w;
            uint32_t hi01, lo01, hi23, lo23;
            bf16split2(s0, s1, hi01, lo01);
            bf16split2(s2, s3, hi23, lo23);
            u64 hiq = ((u64)hi23 << 32) | hi01;
            u64 loq = ((u64)lo23 << 32) | lo01;
            const int px = wbase + sub;
            const uint32_t off = SWB(px, chunk*8);
            *(u64*)(Ahi + off) = hiq;
            *(u64*)(Alo + off) = loq;
        }

        __syncthreads();   // B visible everywhere; own A done (warp-private)

        // ---- MMA: 4 k-steps x 8 n-tiles x 3 split terms ----
        {
            const int arow = wbase + (lane & 15);
            const int acolh = ((lane >> 4) & 1) * 16;
            const int brow_base = lane & 7;
            const int bcolh = ((lane >> 3) & 1) * 16;
            #pragma unroll
            for (int ks = 0; ks < 4; ks++) {
                uint32_t Afh[4], Afl[4];
                uint32_t aoff = SWB(arow, ks*32 + acolh);
                ldsm_x4(Afh, ahi_u + aoff);
                ldsm_x4(Afl, alo_u + aoff);
                #pragma unroll
                for (int nt = 0; nt < 8; nt++) {
                    const int brow = nt*8 + brow_base;
                    uint32_t boff = SWB(brow, ks*32 + bcolh);
                    uint32_t Bfh[2], Bfl[2];
                    ldsm_x2(Bfh, bhi_u + boff);
                    ldsm_x2(Bfl, blo_u + boff);
                    mma16816(C[nt], Afh, Bfh);
                    mma16816(C[nt], Afl, Bfh);
                    mma16816(C[nt], Afh, Bfl);
                }
            }
        }
    }

    // ---- epilogue: C fragment -> out[b][o][h][w] ----
    {
        const int g = lane >> 2, t = lane & 3;
        const int m0 = wbase + g;
        float* ob = out + (size_t)b*CO_*HW_ + h*W_;
        #pragma unroll
        for (int nt = 0; nt < 8; nt++) {
            const int n0 = nt*8 + 2*t;
            ob[(size_t)n0*HW_ + m0]         = C[nt][0];
            ob[(size_t)(n0+1)*HW_ + m0]     = C[nt][1];
            ob[(size_t)n0*HW_ + m0 + 8]     = C[nt][2];
            ob[(size_t)(n0+1)*HW_ + m0 + 8] = C[nt][3];
        }
    }
}

extern "C" void kernel_launch(void* const* d_in, const int* in_sizes, int n_in,
                              void* d_out, int out_size) {
    const float* mem   = (const float*)d_in[0];
    const float* que   = (const float*)d_in[1];
    const float* w_off = (const float*)d_in[2];
    const float* b_off = (const float*)d_in[3];
    const float* w_def = (const float*)d_in[4];
    float* out = (float*)d_out;

    cudaFuncSetAttribute(offset_mma_kernel,
                         cudaFuncAttributeMaxDynamicSharedMemorySize, OSM_BYTES);

    setup_kernel<<<SETUP_BLOCKS, 256>>>(mem, que, w_off, w_def);
    offset_mma_kernel<<<B_*H_, 256, OSM_BYTES>>>(b_off);
    deform_mma_kernel<<<B_*H_, 256>>>(out);
}

// round 17
// speedup vs baseline: 1.5064x; 1.0293x over previous
#include <cuda_runtime.h>
#include <cuda_bf16.h>
#include <cstdint>

typedef unsigned long long u64;

#define B_    8
#define CM_   64
#define CQ_   64
#define CIN_  128
#define CO_   64
#define H_    128
#define W_    128
#define K_    9
#define JOFF_ 27
#define HW_   (H_*W_)

// Scratch (no cudaMalloc allowed).
__device__ __align__(16) float  g_off[B_*JOFF_*HW_];      // [b][j][h][w]
__device__ __align__(16) __nv_bfloat16 g_wbf[K_*2*4096];  // deform W: [tap][hi|lo][n][k]
__device__ __align__(16) __nv_bfloat16 g_wobf[K_*2*2*2048]; // offset W: [tap][half][hi|lo][n=32][k=64]
__device__ __align__(16) float  g_xT[B_*HW_*CIN_];        // channel-last concat [b][h][w][c=128]

__device__ __forceinline__ uint32_t smem_u32(const void* p) {
    uint32_t a;
    asm("{ .reg .u64 t; cvta.to.shared.u64 t, %1; cvt.u32.u64 %0, t; }" : "=r"(a) : "l"(p));
    return a;
}

#define SWB(row, colb) ((row)*128 + ((((colb) >> 4) ^ ((row) & 7)) << 4) + ((colb) & 15))

__device__ __forceinline__ void ldsm_x4(uint32_t a[4], uint32_t addr) {
    asm volatile("ldmatrix.sync.aligned.m8n8.x4.shared.b16 {%0,%1,%2,%3}, [%4];"
        : "=r"(a[0]), "=r"(a[1]), "=r"(a[2]), "=r"(a[3]) : "r"(addr));
}
__device__ __forceinline__ void ldsm_x2(uint32_t b[2], uint32_t addr) {
    asm volatile("ldmatrix.sync.aligned.m8n8.x2.shared.b16 {%0,%1}, [%2];"
        : "=r"(b[0]), "=r"(b[1]) : "r"(addr));
}
__device__ __forceinline__ void mma16816(float c[4], const uint32_t a[4], const uint32_t b[2]) {
    asm volatile("mma.sync.aligned.m16n8k16.row.col.f32.bf16.bf16.f32 "
        "{%0,%1,%2,%3}, {%4,%5,%6,%7}, {%8,%9}, {%0,%1,%2,%3};"
        : "+f"(c[0]), "+f"(c[1]), "+f"(c[2]), "+f"(c[3])
        : "r"(a[0]), "r"(a[1]), "r"(a[2]), "r"(a[3]), "r"(b[0]), "r"(b[1]));
}

// scalar split (prep only)
__device__ __forceinline__ void bf16split(float s, uint16_t &hi, uint16_t &lo) {
    __nv_bfloat16 h = __float2bfloat16_rn(s);
    __nv_bfloat16 l = __float2bfloat16_rn(s - __bfloat162float(h));
    hi = __bfloat16_as_ushort(h);
    lo = __bfloat16_as_ushort(l);
}

// packed split: {s1,s0} -> hi2 = {bf16(s1),bf16(s0)}, lo2 = residual pair.
// Bit-identical to per-value __float2bfloat16_rn.
__device__ __forceinline__ void bf16split2(float s0, float s1,
                                           uint32_t &hi2, uint32_t &lo2) {
    asm("cvt.rn.bf16x2.f32 %0, %1, %2;" : "=r"(hi2) : "f"(s1), "f"(s0));
    float h0 = __uint_as_float(hi2 << 16);
    float h1 = __uint_as_float(hi2 & 0xffff0000u);
    asm("cvt.rn.bf16x2.f32 %0, %1, %2;" : "=r"(lo2) : "f"(s1 - h1), "f"(s0 - h0));
}

// ---------------------------------------------------------------------------
// Prep: deform weights (bf16 hi/lo [n][k]) + offset weights
// ([tap][half][hi|lo][n=32 pad][k=64]). Tiny kernel, 16 regs.
// ---------------------------------------------------------------------------
#define N_WB   (K_*64*64)       // 36864
#define N_WO   (K_*2*32*64)     // 36864
__global__ void prep_weights_kernel(const float* __restrict__ w_off,
                                    const float* __restrict__ w_def) {
    int i = blockIdx.x * 256 + threadIdx.x;
    if (i < N_WB) {
        int tap = i / 4096;
        int r = i - tap*4096;
        int n = r >> 6;
        int c = r & 63;
        float w = w_def[(n*CM_ + c)*K_ + tap];
        uint16_t hi, lo;
        bf16split(w, hi, lo);
        g_wbf[tap*8192 + n*64 + c]        = __ushort_as_bfloat16(hi);
        g_wbf[tap*8192 + 4096 + n*64 + c] = __ushort_as_bfloat16(lo);
    } else if (i < N_WB + N_WO) {
        int i2 = i - N_WB;
        int tap = i2 / 4096;
        int r = i2 - tap*4096;
        int half = r >> 11;
        int r2 = r & 2047;
        int n = r2 >> 6;
        int k = r2 & 63;
        int c = half*64 + k;
        float w = (n < JOFF_) ? w_off[(n*CIN_ + c)*K_ + tap] : 0.f;
        uint16_t hi, lo;
        bf16split(w, hi, lo);
        g_wobf[tap*8192 + half*4096 + n*64 + k]        = __ushort_as_bfloat16(hi);
        g_wobf[tap*8192 + half*4096 + 2048 + n*64 + k] = __ushort_as_bfloat16(lo);
    }
}

// ---------------------------------------------------------------------------
// Transpose concat(mem,que) -> channel-last g_xT[b][h][w][c=128].
// Reg-capped (<=64) + moderate unroll: 4 blocks/SM, BW-bound.
// ---------------------------------------------------------------------------
__global__ __launch_bounds__(256, 4) void transpose_x_kernel(
        const float* __restrict__ mem, const float* __restrict__ que) {
    __shared__ float tile[64][129];
    const int bh = blockIdx.x;
    const int b = bh >> 7, h = bh & 127;
    const int tid = threadIdx.x;
    for (int pass = 0; pass < 2; pass++) {
        const float* src = (pass ? que + (size_t)b*CQ_*HW_ : mem + (size_t)b*CM_*HW_) + h*W_;
        #pragma unroll 8
        for (int m = 0; m < 32; m++) {
            int e = tid + 256*m;
            int c = e >> 7, w = e & 127;
            tile[c][w] = src[(size_t)c*HW_ + w];
        }
        __syncthreads();
        float* dst = g_xT + ((size_t)b*HW_ + h*W_)*CIN_ + pass*64;
        #pragma unroll 8
        for (int m = 0; m < 32; m++) {
            int e = tid + 256*m;
            int w = e >> 6, c = e & 63;
            dst[(size_t)w*CIN_ + c] = tile[c][w];
        }
        __syncthreads();
    }
}

// ---------------------------------------------------------------------------
// Offset conv on mma.sync, halo-A design (frozen structure): 6 stages
// (3 ky x 2 channel-halves), A staged once per stage as 130-row halo tile,
// 3 kx shifts free via ldsm row addressing. Packed bf16 split in staging.
// ---------------------------------------------------------------------------
#define OA_BYTES   16640                  // 130 rows x 128B
#define OB_BASE    (2*OA_BYTES)           // 33280
#define OSM_BYTES  (OB_BASE + 3*8192)     // 57856

__global__ __launch_bounds__(256, 3) void offset_mma_kernel(const float* __restrict__ b_off) {
    extern __shared__ __align__(16) char smem[];
    char* Ahi = smem;
    char* Alo = smem + OA_BYTES;
    const uint32_t ahi_u = smem_u32(Ahi), alo_u = smem_u32(Alo);
    const uint32_t bb_u  = smem_u32(smem + OB_BASE);

    const int tid  = threadIdx.x;
    const int lane = tid & 31;
    const int wrp  = tid >> 5;
    const int bh   = blockIdx.x;
    const int b    = bh >> 7;
    const int h    = bh & 127;
    const int wbase = wrp * 16;

    const char* xTb = (const char*)(g_xT + (size_t)b*HW_*CIN_);

    float C[4][4];
    #pragma unroll
    for (int nt = 0; nt < 4; nt++)
        #pragma unroll
        for (int i = 0; i < 4; i++) C[nt][i] = 0.f;

    #pragma unroll
    for (int st = 0; st < 6; st++) {
        const int ky = st >> 1;
        const int hh = st & 1;              // channel half
        const int rowv = h + ky - 1;
        const bool rowok = (rowv >= 0 && rowv < H_);

        // ---- prefetch B for 3 taps of this ky (fly under previous MMA) ----
        uint4 bv[6];
        #pragma unroll
        for (int m = 0; m < 6; m++) {
            int e = tid + 256*m;            // 0..1535
            int kx = e >> 9;                // 512 uint4 per tap
            bv[m] = ((const uint4*)(g_wobf + (size_t)(ky*3 + kx)*8192 + hh*4096))[e & 511];
        }

        __syncthreads();   // previous stage's MMAs done; smem writable

        // ---- STS B (swizzled), 3 taps ----
        #pragma unroll
        for (int m = 0; m < 6; m++) {
            int e = tid + 256*m;
            int kx = e >> 9;
            int e2 = e & 511;
            int n = (e2 & 255) >> 3, kc = e2 & 7;
            char* dst = smem + OB_BASE + kx*8192 + ((e2 < 256) ? 0 : 4096);
            *(uint4*)(dst + n*128 + ((kc ^ (n & 7)) << 4)) = bv[m];
        }

        // ---- stage A halo tile: rows 0..129, row r = pixel r-1 ----
        {
            const char* xrow = xTb + ((size_t)rowv*W_)*512 + hh*256;
            const int chunk = tid & 15;
            #pragma unroll
            for (int it = 0; it < 9; it++) {
                const int r = (tid >> 4) + 16*it;
                if (r < 130) {
                    const int p = r - 1;
                    float4 v = make_float4(0.f, 0.f, 0.f, 0.f);
                    if (rowok && p >= 0 && p < W_)
                        v = *(const float4*)(xrow + (size_t)p*512 + chunk*16);
                    uint32_t hi01, lo01, hi23, lo23;
                    bf16split2(v.x, v.y, hi01, lo01);
                    bf16split2(v.z, v.w, hi23, lo23);
                    u64 hiq = ((u64)hi23 << 32) | hi01;
                    u64 loq = ((u64)lo23 << 32) | lo01;
                    const uint32_t off = SWB(r, chunk*8);
                    *(u64*)(Ahi + off) = hiq;
                    *(u64*)(Alo + off) = loq;
                }
            }
        }
        __syncthreads();   // A + B ready everywhere

        // ---- MMA: 3 kx passes x 4 k-steps x 4 n-tiles x 3 split terms ----
        {
            const int acolh = ((lane >> 4) & 1) * 16;
            const int brow_base = lane & 7;
            const int bcolh = ((lane >> 3) & 1) * 16;
            #pragma unroll
            for (int kx = 0; kx < 3; kx++) {
                const int arow = wbase + (lane & 15) + kx;   // pixel px+kx-1
                const uint32_t bhi_u = bb_u + kx*8192;
                const uint32_t blo_u = bhi_u + 4096;
                #pragma unroll
                for (int ks = 0; ks < 4; ks++) {
                    uint32_t Afh[4], Afl[4];
                    uint32_t aoff = SWB(arow, ks*32 + acolh);
                    ldsm_x4(Afh, ahi_u + aoff);
                    ldsm_x4(Afl, alo_u + aoff);
                    #pragma unroll
                    for (int nt = 0; nt < 4; nt++) {
                        const int brow = nt*8 + brow_base;
                        uint32_t boff = SWB(brow, ks*32 + bcolh);
                        uint32_t Bfh[2], Bfl[2];
                        ldsm_x2(Bfh, bhi_u + boff);
                        ldsm_x2(Bfl, blo_u + boff);
                        mma16816(C[nt], Afh, Bfh);
                        mma16816(C[nt], Afl, Bfh);
                        mma16816(C[nt], Afh, Bfl);
                    }
                }
            }
        }
    }

    // ---- epilogue: C + bias -> g_off[b][j][h][w], j < 27 ----
    {
        const int g = lane >> 2, t4 = lane & 3;
        const int m0 = wbase + g;
        float* ob = g_off + (size_t)b*JOFF_*HW_ + h*W_;
        #pragma unroll
        for (int nt = 0; nt < 4; nt++) {
            const int n0 = nt*8 + 2*t4;
            if (n0 < JOFF_) {
                float bi = b_off[n0];
                ob[(size_t)n0*HW_ + m0]     = C[nt][0] + bi;
                ob[(size_t)n0*HW_ + m0 + 8] = C[nt][2] + bi;
            }
            if (n0 + 1 < JOFF_) {
                float bi = b_off[n0 + 1];
                ob[(size_t)(n0+1)*HW_ + m0]     = C[nt][1] + bi;
                ob[(size_t)(n0+1)*HW_ + m0 + 8] = C[nt][3] + bi;
            }
        }
    }
}

// ---------------------------------------------------------------------------
// Deformable conv (R12 schedule, frozen): homogeneous warps, params + B LDGs
// before sync1, gather between syncs, M=16/warp, N=64. Packed bf16 split.
// ---------------------------------------------------------------------------
__global__ __launch_bounds__(256, 3) void deform_mma_kernel(float* __restrict__ out) {
    __shared__ __align__(16) char smem[49152];   // Ahi 16K | Alo 16K | Bhi 8K | Blo 8K
    char* Ahi = smem;
    char* Alo = smem + 16384;
    char* Bhi = smem + 32768;
    char* Blo = smem + 40960;
    const uint32_t ahi_u = smem_u32(Ahi), alo_u = smem_u32(Alo);
    const uint32_t bhi_u = smem_u32(Bhi), blo_u = smem_u32(Blo);

    const int tid  = threadIdx.x;
    const int lane = tid & 31;
    const int wrp  = tid >> 5;
    const int bh   = blockIdx.x;
    const int b    = bh >> 7;
    const int h    = bh & 127;
    const int wbase = wrp * 16;
    const int chunk = lane & 15;

    const char* memTb = (const char*)(g_xT + (size_t)b*HW_*CIN_);  // ch 0-63 = mem
    const float* offrow = g_off + (size_t)b*JOFF_*HW_ + h*W_;

    float C[8][4];
    #pragma unroll
    for (int nt = 0; nt < 8; nt++)
        #pragma unroll
        for (int i = 0; i < 4; i++) C[nt][i] = 0.f;

    for (int tap = 0; tap < K_; tap++) {
        // ---- per-warp bilinear params (no smem; LDGs fly under prev MMA) ----
        float W00, W01, W10, W11;
        int   B00, B01, B10, B11;
        {
            const int ppx = wbase + (lane & 15);
            const float* op = offrow + ppx;
            float dy  = op[(2*tap)*HW_];
            float dx  = op[(2*tap+1)*HW_];
            float msk = op[(18+tap)*HW_];
            float py  = (float)(h + (tap/3) - 1) + dy;
            float pxx = (float)(ppx + (tap - (tap/3)*3) - 1) + dx;
            float y0f = floorf(py), x0f = floorf(pxx);
            float fy = py - y0f, fx = pxx - x0f;
            int y0 = (int)y0f, x0 = (int)x0f;
            int y1 = y0 + 1,   x1 = x0 + 1;
            float vy0 = (y0 >= 0 && y0 < H_) ? 1.f : 0.f;
            float vy1 = (y1 >= 0 && y1 < H_) ? 1.f : 0.f;
            float vx0 = (x0 >= 0 && x0 < W_) ? 1.f : 0.f;
            float vx1 = (x1 >= 0 && x1 < W_) ? 1.f : 0.f;
            int y0c = min(max(y0, 0), H_-1), y1c = min(max(y1, 0), H_-1);
            int x0c = min(max(x0, 0), W_-1), x1c = min(max(x1, 0), W_-1);
            W00 = (1.f-fy)*(1.f-fx)*msk*vy0*vx0;
            W01 = (1.f-fy)*fx      *msk*vy0*vx1;
            W10 = fy      *(1.f-fx)*msk*vy1*vx0;
            W11 = fy      *fx      *msk*vy1*vx1;
            B00 = (y0c*W_ + x0c) << 9;    // *512B (128 ch x 4B per pixel)
            B01 = (y0c*W_ + x1c) << 9;
            B10 = (y1c*W_ + x0c) << 9;
            B11 = (y1c*W_ + x1c) << 9;
        }

        // ---- B LDGs early ----
        const uint4* bsrc = (const uint4*)(g_wbf + (size_t)tap*8192);
        uint4 bv[4];
        #pragma unroll
        for (int m = 0; m < 4; m++) bv[m] = bsrc[tid + 256*m];

        __syncthreads();   // previous tap's MMAs done; smem writable

        // ---- STS B (swizzled) ----
        #pragma unroll
        for (int m = 0; m < 4; m++) {
            int e = tid + 256*m;
            int e2 = e & 511;
            int n = e2 >> 3, kc = e2 & 7;
            char* dst = (e < 512) ? Bhi : Blo;
            *(uint4*)(dst + n*128 + ((kc ^ (n & 7)) << 4)) = bv[m];
        }

        // ---- gather: 8 iters x 2 pixels; lane = 16B channel chunk ----
        #pragma unroll
        for (int i = 0; i < 8; i++) {
            const int sub = 2*i + (lane >> 4);
            float w00 = __shfl_sync(0xffffffffu, W00, sub);
            float w01 = __shfl_sync(0xffffffffu, W01, sub);
            float w10 = __shfl_sync(0xffffffffu, W10, sub);
            float w11 = __shfl_sync(0xffffffffu, W11, sub);
            int   b00 = __shfl_sync(0xffffffffu, B00, sub);
            int   b01 = __shfl_sync(0xffffffffu, B01, sub);
            int   b10 = __shfl_sync(0xffffffffu, B10, sub);
            int   b11 = __shfl_sync(0xffffffffu, B11, sub);
            const int cb = chunk * 16;
            float4 c00 = *(const float4*)(memTb + b00 + cb);
            float4 c01 = *(const float4*)(memTb + b01 + cb);
            float4 c10 = *(const float4*)(memTb + b10 + cb);
            float4 c11 = *(const float4*)(memTb + b11 + cb);
            float s0 = w00*c00.x + w01*c01.x + w10*c10.x + w11*c11.x;
            float s1 = w00*c00.y + w01*c01.y + w10*c10.y + w11*c11.y;
            float s2 = w00*c00.z + w01*c01.z + w10*c10.z + w11*c11.z;
            float s3 = w00*c00.w + w01*c01.w + w10*c10.w + w11*c11.w;
            uint32_t hi01, lo01, hi23, lo23;
            bf16split2(s0, s1, hi01, lo01);
            bf16split2(s2, s3, hi23, lo23);
            u64 hiq = ((u64)hi23 << 32) | hi01;
            u64 loq = ((u64)lo23 << 32) | lo01;
            const int px = wbase + sub;
            const uint32_t off = SWB(px, chunk*8);
            *(u64*)(Ahi + off) = hiq;
            *(u64*)(Alo + off) = loq;
        }

        __syncthreads();   // B visible everywhere; own A done (warp-private)

        // ---- MMA: 4 k-steps x 8 n-tiles x 3 split terms ----
        {
            const int arow = wbase + (lane & 15);
            const int acolh = ((lane >> 4) & 1) * 16;
            const int brow_base = lane & 7;
            const int bcolh = ((lane >> 3) & 1) * 16;
            #pragma unroll
            for (int ks = 0; ks < 4; ks++) {
                uint32_t Afh[4], Afl[4];
                uint32_t aoff = SWB(arow, ks*32 + acolh);
                ldsm_x4(Afh, ahi_u + aoff);
                ldsm_x4(Afl, alo_u + aoff);
                #pragma unroll
                for (int nt = 0; nt < 8; nt++) {
                    const int brow = nt*8 + brow_base;
                    uint32_t boff = SWB(brow, ks*32 + bcolh);
                    uint32_t Bfh[2], Bfl[2];
                    ldsm_x2(Bfh, bhi_u + boff);
                    ldsm_x2(Bfl, blo_u + boff);
                    mma16816(C[nt], Afh, Bfh);
                    mma16816(C[nt], Afl, Bfh);
                    mma16816(C[nt], Afh, Bfl);
                }
            }
        }
    }

    // ---- epilogue: C fragment -> out[b][o][h][w] ----
    {
        const int g = lane >> 2, t = lane & 3;
        const int m0 = wbase + g;
        float* ob = out + (size_t)b*CO_*HW_ + h*W_;
        #pragma unroll
        for (int nt = 0; nt < 8; nt++) {
            const int n0 = nt*8 + 2*t;
            ob[(size_t)n0*HW_ + m0]         = C[nt][0];
            ob[(size_t)(n0+1)*HW_ + m0]     = C[nt][1];
            ob[(size_t)n0*HW_ + m0 + 8]     = C[nt][2];
            ob[(size_t)(n0+1)*HW_ + m0 + 8] = C[nt][3];
        }
    }
}

extern "C" void kernel_launch(void* const* d_in, const int* in_sizes, int n_in,
                              void* d_out, int out_size) {
    const float* mem   = (const float*)d_in[0];
    const float* que   = (const float*)d_in[1];
    const float* w_off = (const float*)d_in[2];
    const float* b_off = (const float*)d_in[3];
    const float* w_def = (const float*)d_in[4];
    float* out = (float*)d_out;

    cudaFuncSetAttribute(offset_mma_kernel,
                         cudaFuncAttributeMaxDynamicSharedMemorySize, OSM_BYTES);

    prep_weights_kernel<<<(N_WB + N_WO + 255)/256, 256>>>(w_off, w_def);
    transpose_x_kernel<<<B_*H_, 256>>>(mem, que);
    offset_mma_kernel<<<B_*H_, 256, OSM_BYTES>>>(b_off);
    deform_mma_kernel<<<B_*H_, 256>>>(out);
}